// round 7
// baseline (speedup 1.0000x reference)
#include <cuda_runtime.h>
#include <math.h>

// ---------------- problem constants ----------------
#define BB 2
#define SS 64
#define LL 256
#define CC 192
#define C4 768
#define HH 4
#define DH 48
#define TT (BB*SS*LL)      // 32768 tokens
#define NBLK 6

// ---------------- scratch ----------------
__device__ float g_x[TT*CC];
__device__ float g_h[TT*CC];
__device__ float g_q[TT*CC];
__device__ float g_k[TT*CC];
__device__ float g_v[TT*CC];
__device__ float g_f1[TT*C4];

__device__ __forceinline__ float elu1(float v) { return v > 0.0f ? v + 1.0f : expf(v); }
__device__ __forceinline__ float gelu_exact(float v) {
    return 0.5f * v * (1.0f + erff(v * 0.70710678118654752f));
}

// ============================================================
// Kernel 1: embed + proj + rotary
// ============================================================
__global__ void embed_kernel(const int* __restrict__ tokens,
                             const float* __restrict__ emb,
                             const float* __restrict__ pw,
                             const float* __restrict__ pb,
                             float* __restrict__ out) {
    int t = blockIdx.x;
    int c = threadIdx.x;
    __shared__ float e[64];
    __shared__ float xv[CC];
    __shared__ float invf[96];
    if (c < 64) e[c] = emb[tokens[t] * 64 + c];
    if (c >= 64 && c < 160) {
        int j = c - 64;
        invf[j] = powf(10000.0f, -(float)j / 96.0f);
    }
    __syncthreads();
    float s = pb[c];
    const float* wr = pw + c * 64;
    #pragma unroll
    for (int i = 0; i < 64; i++) s += e[i] * wr[i];
    xv[c] = s;
    __syncthreads();
    int l = t & (LL - 1);
    int c2 = (c < 96) ? c : c - 96;
    float a = (float)l * invf[c2];
    float cs = cosf(a), sn = sinf(a);
    float rot = (c < 96) ? -xv[c + 96] : xv[c - 96];
    out[(size_t)t * CC + c] = s * cs + rot * sn;
}

// ============================================================
// Kernel 2: LayerNorm over channels
// ============================================================
__global__ void ln_kernel(const float* __restrict__ x, float* __restrict__ h,
                          const float* __restrict__ g, const float* __restrict__ b) {
    int t = blockIdx.x * 8 + threadIdx.y;
    int lane = threadIdx.x;
    const float* xr = x + (size_t)t * CC;
    float v[6];
    float s = 0.f, ss = 0.f;
    #pragma unroll
    for (int i = 0; i < 6; i++) {
        v[i] = xr[lane + i * 32];
        s += v[i]; ss += v[i] * v[i];
    }
    #pragma unroll
    for (int o = 16; o; o >>= 1) {
        s  += __shfl_xor_sync(0xffffffffu, s, o);
        ss += __shfl_xor_sync(0xffffffffu, ss, o);
    }
    float m   = s * (1.0f / CC);
    float var = ss * (1.0f / CC) - m * m;
    float r   = rsqrtf(var + 1e-5f);
    float* hr = h + (size_t)t * CC;
    #pragma unroll
    for (int i = 0; i < 6; i++) {
        int c = lane + i * 32;
        hr[c] = (v[i] - m) * r * g[c] + b[c];
    }
}

// ============================================================
// TF32 tensor-core GEMM body, fragment-major shared layout.
// C[t,o] = act( A[t,:K] . W[o,:K] + bias[o] ) (+C)
// Block tile 128x64, 8 warps (4x2), warp 32x32, mma m16n8k8 tf32.
// Shared A: [mtile(8)][ktile(2)][lane(32)][slot(4)]  (float4 per lane)
// Shared B: [ntile(8)][ktile(2)][lane(32)][slot(2)]  (float2 per lane)
// ============================================================
#define BM 128
#define BN 64
#define BK 16

__device__ __forceinline__ void gemm_body(
        const float* __restrict__ A, const float* __restrict__ W,
        const float* __restrict__ bias, float* __restrict__ Cout,
        int K, int N, int act, int accFlag, int rowBlk, int colBlk,
        float* As, float* Bs) {
    int tid  = threadIdx.x;
    int lane = tid & 31;
    int warp = tid >> 5;
    int warpM = warp >> 1;
    int warpN = warp & 1;
    int gid = lane >> 2;
    int tig = lane & 3;
    int row0 = rowBlk * BM;
    int col0 = colBlk * BN;

    float acc[2][4][4];
    #pragma unroll
    for (int i = 0; i < 2; i++)
        #pragma unroll
        for (int j = 0; j < 4; j++)
            #pragma unroll
            for (int q = 0; q < 4; q++) acc[i][j][q] = 0.f;

    // staging indices
    int am = tid >> 1;                 // with i-loop: lin = tid + i*256 -> m = lin>>2... use explicit below
    (void)am;
    float4 aPre[2]; float4 bPre;
    {   // preload k0 = 0
        #pragma unroll
        for (int i = 0; i < 2; i++) {
            int lin = tid + i * 256;
            int m  = lin >> 2;
            int kq = (lin & 3) << 2;
            aPre[i] = *(const float4*)&A[(size_t)(row0 + m) * K + kq];
        }
        int n  = tid >> 2;
        int kq = (tid & 3) << 2;
        bPre = *(const float4*)&W[(size_t)(col0 + n) * K + kq];
    }

    for (int k0 = 0; k0 < K; k0 += BK) {
        // ---- store staged regs into fragment-major smem ----
        #pragma unroll
        for (int i = 0; i < 2; i++) {
            int lin = tid + i * 256;
            int m  = lin >> 2;
            int kq = (lin & 3) << 2;
            int mtile = m >> 4, r = m & 15;
            float fv[4] = {aPre[i].x, aPre[i].y, aPre[i].z, aPre[i].w};
            #pragma unroll
            for (int j = 0; j < 4; j++) {
                int k = kq + j;
                int ktile = k >> 3, kk = k & 7;
                int idx = (((mtile * 2 + ktile) * 32) + (r & 7) * 4 + (kk & 3)) * 4
                          + (r >> 3) + ((kk >> 2) << 1);
                As[idx] = fv[j];
            }
        }
        {
            int n  = tid >> 2;
            int kq = (tid & 3) << 2;
            int ntile = n >> 3, c = n & 7;
            float fv[4] = {bPre.x, bPre.y, bPre.z, bPre.w};
            #pragma unroll
            for (int j = 0; j < 4; j++) {
                int k = kq + j;
                int ktile = k >> 3, kk = k & 7;
                int idx = (((ntile * 2 + ktile) * 32) + c * 4 + (kk & 3)) * 2 + (kk >> 2);
                Bs[idx] = fv[j];
            }
        }
        __syncthreads();

        // ---- prefetch next k-tile ----
        if (k0 + BK < K) {
            #pragma unroll
            for (int i = 0; i < 2; i++) {
                int lin = tid + i * 256;
                int m  = lin >> 2;
                int kq = (lin & 3) << 2;
                aPre[i] = *(const float4*)&A[(size_t)(row0 + m) * K + k0 + BK + kq];
            }
            int n  = tid >> 2;
            int kq = (tid & 3) << 2;
            bPre = *(const float4*)&W[(size_t)(col0 + n) * K + k0 + BK + kq];
        }

        // ---- compute ----
        #pragma unroll
        for (int ktile = 0; ktile < 2; ktile++) {
            float4 af[2]; float2 bf[4];
            #pragma unroll
            for (int mt = 0; mt < 2; mt++) {
                int mtile = warpM * 2 + mt;
                af[mt] = ((const float4*)As)[(mtile * 2 + ktile) * 32 + lane];
            }
            #pragma unroll
            for (int nt = 0; nt < 4; nt++) {
                int ntile = warpN * 4 + nt;
                bf[nt] = ((const float2*)Bs)[(ntile * 2 + ktile) * 32 + lane];
            }
            #pragma unroll
            for (int mt = 0; mt < 2; mt++)
                #pragma unroll
                for (int nt = 0; nt < 4; nt++) {
                    asm volatile(
                        "mma.sync.aligned.m16n8k8.row.col.f32.tf32.tf32.f32 "
                        "{%0,%1,%2,%3}, {%4,%5,%6,%7}, {%8,%9}, {%0,%1,%2,%3};"
                        : "+f"(acc[mt][nt][0]), "+f"(acc[mt][nt][1]),
                          "+f"(acc[mt][nt][2]), "+f"(acc[mt][nt][3])
                        : "r"(__float_as_uint(af[mt].x)), "r"(__float_as_uint(af[mt].y)),
                          "r"(__float_as_uint(af[mt].z)), "r"(__float_as_uint(af[mt].w)),
                          "r"(__float_as_uint(bf[nt].x)), "r"(__float_as_uint(bf[nt].y)));
                }
        }
        __syncthreads();
    }

    #pragma unroll
    for (int mt = 0; mt < 2; mt++) {
        int r0 = row0 + warpM * 32 + mt * 16 + gid;
        #pragma unroll
        for (int nt = 0; nt < 4; nt++) {
            int c0 = col0 + warpN * 32 + nt * 8 + tig * 2;
            #pragma unroll
            for (int half = 0; half < 2; half++) {
                int r = r0 + half * 8;
                #pragma unroll
                for (int q = 0; q < 2; q++) {
                    int c = c0 + q;
                    float v = acc[mt][nt][half * 2 + q] + bias[c];
                    if (act == 1)      v = elu1(v) * 0.14433756729740643f;
                    else if (act == 2) v = elu1(v);
                    else if (act == 3) v = gelu_exact(v);
                    size_t idx = (size_t)r * N + c;
                    if (accFlag) v += Cout[idx];
                    Cout[idx] = v;
                }
            }
        }
    }
}

__global__ __launch_bounds__(256) void gemm_kernel(
        const float* __restrict__ A, const float* __restrict__ W,
        const float* __restrict__ bias, float* __restrict__ Cout,
        int K, int N, int act, int accFlag) {
    __shared__ float As[BM * BK];
    __shared__ float Bs[BN * BK];
    gemm_body(A, W, bias, Cout, K, N, act, accFlag, blockIdx.x, blockIdx.y, As, Bs);
}

// fused Q/K/V: blockIdx.y in [0,9): sel = y/3 chooses {q,k,v}, colBlk = y%3
__global__ __launch_bounds__(256) void qkv_kernel(
        const float* __restrict__ A,
        const float* __restrict__ wq, const float* __restrict__ wk, const float* __restrict__ wv,
        const float* __restrict__ bq, const float* __restrict__ bk, const float* __restrict__ bv,
        float* __restrict__ oq, float* __restrict__ ok, float* __restrict__ ov) {
    __shared__ float As[BM * BK];
    __shared__ float Bs[BN * BK];
    int sel = blockIdx.y / 3;
    int cb  = blockIdx.y % 3;
    const float* W  = sel == 0 ? wq : (sel == 1 ? wk : wv);
    const float* bi = sel == 0 ? bq : (sel == 1 ? bk : bv);
    float* Cout     = sel == 0 ? oq : (sel == 1 ? ok : ov);
    int act         = sel == 0 ? 1  : (sel == 1 ? 2  : 0);
    gemm_body(A, W, bi, Cout, CC, CC, act, 0, blockIdx.x, cb, As, Bs);
}

// ============================================================
// Kernel 4: linear attention core per (group, head)
// kv phase: 3x3 register tile per thread (16x16 thread grid covers 48x48)
// ============================================================
__global__ __launch_bounds__(256) void attn_kernel(
        const float* __restrict__ q, const float* __restrict__ k,
        const float* __restrict__ v, float* __restrict__ o,
        int N, int isCol) {
    extern __shared__ float sm[];
    float* ks   = sm;                 // N*48
    float* vs   = sm + N * DH;        // N*48
    float* kv   = vs + N * DH;        // 48*48
    float* ksum = kv + DH * DH;       // 48
    int g = blockIdx.x, h = blockIdx.y;
    int tid = threadIdx.x;

    for (int lin = tid; lin < N * (DH / 4); lin += 256) {
        int n = lin / (DH / 4);
        int j = lin - n * (DH / 4);
        int t = isCol ? ((((g >> 8) * SS + n) << 8) + (g & 255)) : g * N + n;
        size_t base = (size_t)t * CC + h * DH;
        ((float4*)ks)[n * (DH / 4) + j] = *(const float4*)(k + base + j * 4);
        ((float4*)vs)[n * (DH / 4) + j] = *(const float4*)(v + base + j * 4);
    }
    __syncthreads();

    if (tid < DH) {
        float s = 0.f;
        for (int n = 0; n < N; n++) s += ks[n * DH + tid];
        ksum[tid] = s;
    }
    // kv: 3x3 per-thread register tile
    {
        int dt = (tid >> 4) * 3;   // 0..45
        int et = (tid & 15) * 3;
        float c9[3][3];
        #pragma unroll
        for (int i = 0; i < 3; i++)
            #pragma unroll
            for (int j = 0; j < 3; j++) c9[i][j] = 0.f;
        for (int n = 0; n < N; n++) {
            float kk0 = ks[n * DH + dt],     kk1 = ks[n * DH + dt + 1], kk2 = ks[n * DH + dt + 2];
            float vv0 = vs[n * DH + et],     vv1 = vs[n * DH + et + 1], vv2 = vs[n * DH + et + 2];
            c9[0][0] += kk0 * vv0; c9[0][1] += kk0 * vv1; c9[0][2] += kk0 * vv2;
            c9[1][0] += kk1 * vv0; c9[1][1] += kk1 * vv1; c9[1][2] += kk1 * vv2;
            c9[2][0] += kk2 * vv0; c9[2][1] += kk2 * vv1; c9[2][2] += kk2 * vv2;
        }
        #pragma unroll
        for (int i = 0; i < 3; i++)
            #pragma unroll
            for (int j = 0; j < 3; j++)
                kv[(dt + i) * DH + et + j] = c9[i][j];
    }
    __syncthreads();

    for (int n = tid; n < N; n += 256) {
        int t = isCol ? ((((g >> 8) * SS + n) << 8) + (g & 255)) : g * N + n;
        size_t base = (size_t)t * CC + h * DH;
        float qr[DH];
        #pragma unroll
        for (int j = 0; j < DH / 4; j++) {
            float4 f = *(const float4*)(q + base + j * 4);
            qr[4*j] = f.x; qr[4*j+1] = f.y; qr[4*j+2] = f.z; qr[4*j+3] = f.w;
        }
        float qk = 0.f;
        #pragma unroll
        for (int d = 0; d < DH; d++) qk += qr[d] * ksum[d];
        float z = 1.0f / (qk + 1e-6f);
        float ov[DH];
        #pragma unroll
        for (int e = 0; e < DH; e++) ov[e] = 0.f;
        #pragma unroll
        for (int d = 0; d < DH; d++) {
            float qd = qr[d];
            const float4* kvr = (const float4*)&kv[d * DH];
            #pragma unroll
            for (int j = 0; j < DH / 4; j++) {
                float4 kk4 = kvr[j];
                ov[4*j]   += qd * kk4.x;
                ov[4*j+1] += qd * kk4.y;
                ov[4*j+2] += qd * kk4.z;
                ov[4*j+3] += qd * kk4.w;
            }
        }
        #pragma unroll
        for (int j = 0; j < DH / 4; j++) {
            float4 w4 = make_float4(ov[4*j]*z, ov[4*j+1]*z, ov[4*j+2]*z, ov[4*j+3]*z);
            *(float4*)(o + base + j * 4) = w4;
        }
    }
}

// ============================================================
// Kernel 5: head
// ============================================================
__global__ void final_kernel(const float* __restrict__ x,
                             const float* __restrict__ pw,
                             const float* __restrict__ pb,
                             float* __restrict__ out) {
    int t = blockIdx.x * 8 + threadIdx.y;
    int lane = threadIdx.x;
    const float* xr = x + (size_t)t * CC;
    float s = 0.f;
    #pragma unroll
    for (int i = 0; i < 6; i++) {
        int c = lane + i * 32;
        s += xr[c] * pw[c];
    }
    #pragma unroll
    for (int o = 16; o; o >>= 1) s += __shfl_xor_sync(0xffffffffu, s, o);
    if (lane == 0) {
        float ov = s + pb[0];
        float sp = (ov > 20.f) ? ov : log1pf(expf(ov));
        out[t] = 1.0f / (1.0f + expf(-sp));
    }
}

// ============================================================
// Host orchestration
// ============================================================
extern "C" void kernel_launch(void* const* d_in, const int* in_sizes, int n_in,
                              void* d_out, int out_size) {
    const int*   tokens = (const int*)  d_in[0];
    const float* emb    = (const float*)d_in[1];
    const float* proj_w = (const float*)d_in[2];
    const float* proj_b = (const float*)d_in[3];
    const float* ln_g   = (const float*)d_in[4];
    const float* ln_b   = (const float*)d_in[5];
    const float* wq     = (const float*)d_in[6];
    const float* wk     = (const float*)d_in[7];
    const float* wv     = (const float*)d_in[8];
    const float* wo     = (const float*)d_in[9];
    const float* bq     = (const float*)d_in[10];
    const float* bk     = (const float*)d_in[11];
    const float* bv     = (const float*)d_in[12];
    const float* bo     = (const float*)d_in[13];
    const float* ffn_w1 = (const float*)d_in[14];
    const float* ffn_b1 = (const float*)d_in[15];
    const float* ffn_w2 = (const float*)d_in[16];
    const float* ffn_b2 = (const float*)d_in[17];
    const float* pw_w   = (const float*)d_in[18];
    const float* pw_b   = (const float*)d_in[19];
    float* out = (float*)d_out;

    float *px, *ph, *pq, *pk, *pv, *pf;
    cudaGetSymbolAddress((void**)&px, g_x);
    cudaGetSymbolAddress((void**)&ph, g_h);
    cudaGetSymbolAddress((void**)&pq, g_q);
    cudaGetSymbolAddress((void**)&pk, g_k);
    cudaGetSymbolAddress((void**)&pv, g_v);
    cudaGetSymbolAddress((void**)&pf, g_f1);

    cudaFuncSetAttribute(attn_kernel, cudaFuncAttributeMaxDynamicSharedMemorySize, 110592);

    dim3 lnBlk(32, 8);
    dim3 gQKV(TT / BM, 9);
    dim3 g192(TT / BM, CC / BN);
    dim3 g768(TT / BM, C4 / BN);

    embed_kernel<<<TT, CC>>>(tokens, emb, proj_w, proj_b, px);

    for (int i = 0; i < NBLK; i++) {
        for (int dir = 0; dir < 2; dir++) {
            const float* lg = ln_g + (size_t)(i * 3 + dir) * CC;
            const float* lb = ln_b + (size_t)(i * 3 + dir) * CC;
            ln_kernel<<<TT / 8, lnBlk>>>(px, ph, lg, lb);

            size_t woff = ((size_t)i * 2 + dir) * CC * CC;
            size_t boff = ((size_t)i * 2 + dir) * CC;
            qkv_kernel<<<gQKV, 256>>>(ph, wq + woff, wk + woff, wv + woff,
                                      bq + boff, bk + boff, bv + boff, pq, pk, pv);

            int N      = (dir == 0) ? LL : SS;
            int groups = (dir == 0) ? BB * SS : BB * LL;
            size_t smem = (size_t)(2 * N * DH + DH * DH + DH) * sizeof(float);
            attn_kernel<<<dim3(groups, HH), 256, smem>>>(pq, pk, pv, ph, N, dir);

            gemm_kernel<<<g192, 256>>>(ph, wo + woff, bo + boff, px, CC, CC, 0, 1);
        }
        const float* lg = ln_g + (size_t)(i * 3 + 2) * CC;
        const float* lb = ln_b + (size_t)(i * 3 + 2) * CC;
        ln_kernel<<<TT / 8, lnBlk>>>(px, ph, lg, lb);
        gemm_kernel<<<g768, 256>>>(ph, ffn_w1 + (size_t)i * C4 * CC, ffn_b1 + (size_t)i * C4,
                                   pf, CC, C4, 3, 0);
        gemm_kernel<<<g192, 256>>>(pf, ffn_w2 + (size_t)i * CC * C4, ffn_b2 + (size_t)i * CC,
                                   px, C4, CC, 0, 1);
    }

    final_kernel<<<TT / 8, lnBlk>>>(px, pw_w, pw_b, out);
}

// round 8
// speedup vs baseline: 1.0006x; 1.0006x over previous
#include <cuda_runtime.h>
#include <math.h>

// ---------------- problem constants ----------------
#define BB 2
#define SS 64
#define LL 256
#define CC 192
#define C4 768
#define HH 4
#define DH 48
#define TT (BB*SS*LL)      // 32768 tokens
#define NBLK 6

// ---------------- scratch ----------------
__device__ float g_x[TT*CC];
__device__ float g_h[TT*CC];
__device__ float g_q[TT*CC];
__device__ float g_k[TT*CC];
__device__ float g_v[TT*CC];
__device__ float g_f1[TT*C4];

__device__ __forceinline__ float elu1(float v) { return v > 0.0f ? v + 1.0f : expf(v); }
__device__ __forceinline__ float gelu_exact(float v) {
    return 0.5f * v * (1.0f + erff(v * 0.70710678118654752f));
}

// ============================================================
// Kernel 1: embed + proj + rotary
// ============================================================
__global__ void embed_kernel(const int* __restrict__ tokens,
                             const float* __restrict__ emb,
                             const float* __restrict__ pw,
                             const float* __restrict__ pb,
                             float* __restrict__ out) {
    int t = blockIdx.x;
    int c = threadIdx.x;
    __shared__ float e[64];
    __shared__ float xv[CC];
    __shared__ float invf[96];
    if (c < 64) e[c] = emb[tokens[t] * 64 + c];
    if (c >= 64 && c < 160) {
        int j = c - 64;
        invf[j] = powf(10000.0f, -(float)j / 96.0f);
    }
    __syncthreads();
    float s = pb[c];
    const float* wr = pw + c * 64;
    #pragma unroll
    for (int i = 0; i < 64; i++) s += e[i] * wr[i];
    xv[c] = s;
    __syncthreads();
    int l = t & (LL - 1);
    int c2 = (c < 96) ? c : c - 96;
    float a = (float)l * invf[c2];
    float cs = cosf(a), sn = sinf(a);
    float rot = (c < 96) ? -xv[c + 96] : xv[c - 96];
    out[(size_t)t * CC + c] = s * cs + rot * sn;
}

// ============================================================
// Kernel 2: LayerNorm over channels
// ============================================================
__global__ void ln_kernel(const float* __restrict__ x, float* __restrict__ h,
                          const float* __restrict__ g, const float* __restrict__ b) {
    int t = blockIdx.x * 8 + threadIdx.y;
    int lane = threadIdx.x;
    const float* xr = x + (size_t)t * CC;
    float v[6];
    float s = 0.f, ss = 0.f;
    #pragma unroll
    for (int i = 0; i < 6; i++) {
        v[i] = xr[lane + i * 32];
        s += v[i]; ss += v[i] * v[i];
    }
    #pragma unroll
    for (int o = 16; o; o >>= 1) {
        s  += __shfl_xor_sync(0xffffffffu, s, o);
        ss += __shfl_xor_sync(0xffffffffu, ss, o);
    }
    float m   = s * (1.0f / CC);
    float var = ss * (1.0f / CC) - m * m;
    float r   = rsqrtf(var + 1e-5f);
    float* hr = h + (size_t)t * CC;
    #pragma unroll
    for (int i = 0; i < 6; i++) {
        int c = lane + i * 32;
        hr[c] = (v[i] - m) * r * g[c] + b[c];
    }
}

// ============================================================
// TF32 tensor-core GEMM body, fragment-major shared layout.
// C[t,o] = act( A[t,:K] . W[o,:K] + bias[o] ) (+C)
// Block tile 128x64, 8 warps (4x2), warp 32x32, mma m16n8k8 tf32.
// Shared A: [mtile(8)][ktile(2)][lane(32)][slot(4)]  (float4 per lane)
// Shared B: [ntile(8)][ktile(2)][lane(32)][slot(2)]  (float2 per lane)
// ============================================================
#define BM 128
#define BN 64
#define BK 16

__device__ __forceinline__ void gemm_body(
        const float* __restrict__ A, const float* __restrict__ W,
        const float* __restrict__ bias, float* __restrict__ Cout,
        int K, int N, int act, int accFlag, int rowBlk, int colBlk,
        float* As, float* Bs) {
    int tid  = threadIdx.x;
    int lane = tid & 31;
    int warp = tid >> 5;
    int warpM = warp >> 1;
    int warpN = warp & 1;
    int gid = lane >> 2;
    int tig = lane & 3;
    int row0 = rowBlk * BM;
    int col0 = colBlk * BN;

    float acc[2][4][4];
    #pragma unroll
    for (int i = 0; i < 2; i++)
        #pragma unroll
        for (int j = 0; j < 4; j++)
            #pragma unroll
            for (int q = 0; q < 4; q++) acc[i][j][q] = 0.f;

    // staging indices
    int am = tid >> 1;                 // with i-loop: lin = tid + i*256 -> m = lin>>2... use explicit below
    (void)am;
    float4 aPre[2]; float4 bPre;
    {   // preload k0 = 0
        #pragma unroll
        for (int i = 0; i < 2; i++) {
            int lin = tid + i * 256;
            int m  = lin >> 2;
            int kq = (lin & 3) << 2;
            aPre[i] = *(const float4*)&A[(size_t)(row0 + m) * K + kq];
        }
        int n  = tid >> 2;
        int kq = (tid & 3) << 2;
        bPre = *(const float4*)&W[(size_t)(col0 + n) * K + kq];
    }

    for (int k0 = 0; k0 < K; k0 += BK) {
        // ---- store staged regs into fragment-major smem ----
        #pragma unroll
        for (int i = 0; i < 2; i++) {
            int lin = tid + i * 256;
            int m  = lin >> 2;
            int kq = (lin & 3) << 2;
            int mtile = m >> 4, r = m & 15;
            float fv[4] = {aPre[i].x, aPre[i].y, aPre[i].z, aPre[i].w};
            #pragma unroll
            for (int j = 0; j < 4; j++) {
                int k = kq + j;
                int ktile = k >> 3, kk = k & 7;
                int idx = (((mtile * 2 + ktile) * 32) + (r & 7) * 4 + (kk & 3)) * 4
                          + (r >> 3) + ((kk >> 2) << 1);
                As[idx] = fv[j];
            }
        }
        {
            int n  = tid >> 2;
            int kq = (tid & 3) << 2;
            int ntile = n >> 3, c = n & 7;
            float fv[4] = {bPre.x, bPre.y, bPre.z, bPre.w};
            #pragma unroll
            for (int j = 0; j < 4; j++) {
                int k = kq + j;
                int ktile = k >> 3, kk = k & 7;
                int idx = (((ntile * 2 + ktile) * 32) + c * 4 + (kk & 3)) * 2 + (kk >> 2);
                Bs[idx] = fv[j];
            }
        }
        __syncthreads();

        // ---- prefetch next k-tile ----
        if (k0 + BK < K) {
            #pragma unroll
            for (int i = 0; i < 2; i++) {
                int lin = tid + i * 256;
                int m  = lin >> 2;
                int kq = (lin & 3) << 2;
                aPre[i] = *(const float4*)&A[(size_t)(row0 + m) * K + k0 + BK + kq];
            }
            int n  = tid >> 2;
            int kq = (tid & 3) << 2;
            bPre = *(const float4*)&W[(size_t)(col0 + n) * K + k0 + BK + kq];
        }

        // ---- compute ----
        #pragma unroll
        for (int ktile = 0; ktile < 2; ktile++) {
            float4 af[2]; float2 bf[4];
            #pragma unroll
            for (int mt = 0; mt < 2; mt++) {
                int mtile = warpM * 2 + mt;
                af[mt] = ((const float4*)As)[(mtile * 2 + ktile) * 32 + lane];
            }
            #pragma unroll
            for (int nt = 0; nt < 4; nt++) {
                int ntile = warpN * 4 + nt;
                bf[nt] = ((const float2*)Bs)[(ntile * 2 + ktile) * 32 + lane];
            }
            #pragma unroll
            for (int mt = 0; mt < 2; mt++)
                #pragma unroll
                for (int nt = 0; nt < 4; nt++) {
                    asm volatile(
                        "mma.sync.aligned.m16n8k8.row.col.f32.tf32.tf32.f32 "
                        "{%0,%1,%2,%3}, {%4,%5,%6,%7}, {%8,%9}, {%0,%1,%2,%3};"
                        : "+f"(acc[mt][nt][0]), "+f"(acc[mt][nt][1]),
                          "+f"(acc[mt][nt][2]), "+f"(acc[mt][nt][3])
                        : "r"(__float_as_uint(af[mt].x)), "r"(__float_as_uint(af[mt].y)),
                          "r"(__float_as_uint(af[mt].z)), "r"(__float_as_uint(af[mt].w)),
                          "r"(__float_as_uint(bf[nt].x)), "r"(__float_as_uint(bf[nt].y)));
                }
        }
        __syncthreads();
    }

    #pragma unroll
    for (int mt = 0; mt < 2; mt++) {
        int r0 = row0 + warpM * 32 + mt * 16 + gid;
        #pragma unroll
        for (int nt = 0; nt < 4; nt++) {
            int c0 = col0 + warpN * 32 + nt * 8 + tig * 2;
            #pragma unroll
            for (int half = 0; half < 2; half++) {
                int r = r0 + half * 8;
                #pragma unroll
                for (int q = 0; q < 2; q++) {
                    int c = c0 + q;
                    float v = acc[mt][nt][half * 2 + q] + bias[c];
                    if (act == 1)      v = elu1(v) * 0.14433756729740643f;
                    else if (act == 2) v = elu1(v);
                    else if (act == 3) v = gelu_exact(v);
                    size_t idx = (size_t)r * N + c;
                    if (accFlag) v += Cout[idx];
                    Cout[idx] = v;
                }
            }
        }
    }
}

__global__ __launch_bounds__(256) void gemm_kernel(
        const float* __restrict__ A, const float* __restrict__ W,
        const float* __restrict__ bias, float* __restrict__ Cout,
        int K, int N, int act, int accFlag) {
    __shared__ float As[BM * BK];
    __shared__ float Bs[BN * BK];
    gemm_body(A, W, bias, Cout, K, N, act, accFlag, blockIdx.x, blockIdx.y, As, Bs);
}

// fused Q/K/V: blockIdx.y in [0,9): sel = y/3 chooses {q,k,v}, colBlk = y%3
__global__ __launch_bounds__(256) void qkv_kernel(
        const float* __restrict__ A,
        const float* __restrict__ wq, const float* __restrict__ wk, const float* __restrict__ wv,
        const float* __restrict__ bq, const float* __restrict__ bk, const float* __restrict__ bv,
        float* __restrict__ oq, float* __restrict__ ok, float* __restrict__ ov) {
    __shared__ float As[BM * BK];
    __shared__ float Bs[BN * BK];
    int sel = blockIdx.y / 3;
    int cb  = blockIdx.y % 3;
    const float* W  = sel == 0 ? wq : (sel == 1 ? wk : wv);
    const float* bi = sel == 0 ? bq : (sel == 1 ? bk : bv);
    float* Cout     = sel == 0 ? oq : (sel == 1 ? ok : ov);
    int act         = sel == 0 ? 1  : (sel == 1 ? 2  : 0);
    gemm_body(A, W, bi, Cout, CC, CC, act, 0, blockIdx.x, cb, As, Bs);
}

// ============================================================
// Kernel 4: linear attention core per (group, head)
// kv phase: 3x3 register tile per thread (16x16 thread grid covers 48x48)
// ============================================================
__global__ __launch_bounds__(256) void attn_kernel(
        const float* __restrict__ q, const float* __restrict__ k,
        const float* __restrict__ v, float* __restrict__ o,
        int N, int isCol) {
    extern __shared__ float sm[];
    float* ks   = sm;                 // N*48
    float* vs   = sm + N * DH;        // N*48
    float* kv   = vs + N * DH;        // 48*48
    float* ksum = kv + DH * DH;       // 48
    int g = blockIdx.x, h = blockIdx.y;
    int tid = threadIdx.x;

    for (int lin = tid; lin < N * (DH / 4); lin += 256) {
        int n = lin / (DH / 4);
        int j = lin - n * (DH / 4);
        int t = isCol ? ((((g >> 8) * SS + n) << 8) + (g & 255)) : g * N + n;
        size_t base = (size_t)t * CC + h * DH;
        ((float4*)ks)[n * (DH / 4) + j] = *(const float4*)(k + base + j * 4);
        ((float4*)vs)[n * (DH / 4) + j] = *(const float4*)(v + base + j * 4);
    }
    __syncthreads();

    if (tid < DH) {
        float s = 0.f;
        for (int n = 0; n < N; n++) s += ks[n * DH + tid];
        ksum[tid] = s;
    }
    // kv: 3x3 per-thread register tile
    {
        int dt = (tid >> 4) * 3;   // 0..45
        int et = (tid & 15) * 3;
        float c9[3][3];
        #pragma unroll
        for (int i = 0; i < 3; i++)
            #pragma unroll
            for (int j = 0; j < 3; j++) c9[i][j] = 0.f;
        for (int n = 0; n < N; n++) {
            float kk0 = ks[n * DH + dt],     kk1 = ks[n * DH + dt + 1], kk2 = ks[n * DH + dt + 2];
            float vv0 = vs[n * DH + et],     vv1 = vs[n * DH + et + 1], vv2 = vs[n * DH + et + 2];
            c9[0][0] += kk0 * vv0; c9[0][1] += kk0 * vv1; c9[0][2] += kk0 * vv2;
            c9[1][0] += kk1 * vv0; c9[1][1] += kk1 * vv1; c9[1][2] += kk1 * vv2;
            c9[2][0] += kk2 * vv0; c9[2][1] += kk2 * vv1; c9[2][2] += kk2 * vv2;
        }
        #pragma unroll
        for (int i = 0; i < 3; i++)
            #pragma unroll
            for (int j = 0; j < 3; j++)
                kv[(dt + i) * DH + et + j] = c9[i][j];
    }
    __syncthreads();

    for (int n = tid; n < N; n += 256) {
        int t = isCol ? ((((g >> 8) * SS + n) << 8) + (g & 255)) : g * N + n;
        size_t base = (size_t)t * CC + h * DH;
        float qr[DH];
        #pragma unroll
        for (int j = 0; j < DH / 4; j++) {
            float4 f = *(const float4*)(q + base + j * 4);
            qr[4*j] = f.x; qr[4*j+1] = f.y; qr[4*j+2] = f.z; qr[4*j+3] = f.w;
        }
        float qk = 0.f;
        #pragma unroll
        for (int d = 0; d < DH; d++) qk += qr[d] * ksum[d];
        float z = 1.0f / (qk + 1e-6f);
        float ov[DH];
        #pragma unroll
        for (int e = 0; e < DH; e++) ov[e] = 0.f;
        #pragma unroll
        for (int d = 0; d < DH; d++) {
            float qd = qr[d];
            const float4* kvr = (const float4*)&kv[d * DH];
            #pragma unroll
            for (int j = 0; j < DH / 4; j++) {
                float4 kk4 = kvr[j];
                ov[4*j]   += qd * kk4.x;
                ov[4*j+1] += qd * kk4.y;
                ov[4*j+2] += qd * kk4.z;
                ov[4*j+3] += qd * kk4.w;
            }
        }
        #pragma unroll
        for (int j = 0; j < DH / 4; j++) {
            float4 w4 = make_float4(ov[4*j]*z, ov[4*j+1]*z, ov[4*j+2]*z, ov[4*j+3]*z);
            *(float4*)(o + base + j * 4) = w4;
        }
    }
}

// ============================================================
// Kernel 5: head
// ============================================================
__global__ void final_kernel(const float* __restrict__ x,
                             const float* __restrict__ pw,
                             const float* __restrict__ pb,
                             float* __restrict__ out) {
    int t = blockIdx.x * 8 + threadIdx.y;
    int lane = threadIdx.x;
    const float* xr = x + (size_t)t * CC;
    float s = 0.f;
    #pragma unroll
    for (int i = 0; i < 6; i++) {
        int c = lane + i * 32;
        s += xr[c] * pw[c];
    }
    #pragma unroll
    for (int o = 16; o; o >>= 1) s += __shfl_xor_sync(0xffffffffu, s, o);
    if (lane == 0) {
        float ov = s + pb[0];
        float sp = (ov > 20.f) ? ov : log1pf(expf(ov));
        out[t] = 1.0f / (1.0f + expf(-sp));
    }
}

// ============================================================
// Host orchestration
// ============================================================
extern "C" void kernel_launch(void* const* d_in, const int* in_sizes, int n_in,
                              void* d_out, int out_size) {
    const int*   tokens = (const int*)  d_in[0];
    const float* emb    = (const float*)d_in[1];
    const float* proj_w = (const float*)d_in[2];
    const float* proj_b = (const float*)d_in[3];
    const float* ln_g   = (const float*)d_in[4];
    const float* ln_b   = (const float*)d_in[5];
    const float* wq     = (const float*)d_in[6];
    const float* wk     = (const float*)d_in[7];
    const float* wv     = (const float*)d_in[8];
    const float* wo     = (const float*)d_in[9];
    const float* bq     = (const float*)d_in[10];
    const float* bk     = (const float*)d_in[11];
    const float* bv     = (const float*)d_in[12];
    const float* bo     = (const float*)d_in[13];
    const float* ffn_w1 = (const float*)d_in[14];
    const float* ffn_b1 = (const float*)d_in[15];
    const float* ffn_w2 = (const float*)d_in[16];
    const float* ffn_b2 = (const float*)d_in[17];
    const float* pw_w   = (const float*)d_in[18];
    const float* pw_b   = (const float*)d_in[19];
    float* out = (float*)d_out;

    float *px, *ph, *pq, *pk, *pv, *pf;
    cudaGetSymbolAddress((void**)&px, g_x);
    cudaGetSymbolAddress((void**)&ph, g_h);
    cudaGetSymbolAddress((void**)&pq, g_q);
    cudaGetSymbolAddress((void**)&pk, g_k);
    cudaGetSymbolAddress((void**)&pv, g_v);
    cudaGetSymbolAddress((void**)&pf, g_f1);

    cudaFuncSetAttribute(attn_kernel, cudaFuncAttributeMaxDynamicSharedMemorySize, 110592);

    dim3 lnBlk(32, 8);
    dim3 gQKV(TT / BM, 9);
    dim3 g192(TT / BM, CC / BN);
    dim3 g768(TT / BM, C4 / BN);

    embed_kernel<<<TT, CC>>>(tokens, emb, proj_w, proj_b, px);

    for (int i = 0; i < NBLK; i++) {
        for (int dir = 0; dir < 2; dir++) {
            const float* lg = ln_g + (size_t)(i * 3 + dir) * CC;
            const float* lb = ln_b + (size_t)(i * 3 + dir) * CC;
            ln_kernel<<<TT / 8, lnBlk>>>(px, ph, lg, lb);

            size_t woff = ((size_t)i * 2 + dir) * CC * CC;
            size_t boff = ((size_t)i * 2 + dir) * CC;
            qkv_kernel<<<gQKV, 256>>>(ph, wq + woff, wk + woff, wv + woff,
                                      bq + boff, bk + boff, bv + boff, pq, pk, pv);

            int N      = (dir == 0) ? LL : SS;
            int groups = (dir == 0) ? BB * SS : BB * LL;
            size_t smem = (size_t)(2 * N * DH + DH * DH + DH) * sizeof(float);
            attn_kernel<<<dim3(groups, HH), 256, smem>>>(pq, pk, pv, ph, N, dir);

            gemm_kernel<<<g192, 256>>>(ph, wo + woff, bo + boff, px, CC, CC, 0, 1);
        }
        const float* lg = ln_g + (size_t)(i * 3 + 2) * CC;
        const float* lb = ln_b + (size_t)(i * 3 + 2) * CC;
        ln_kernel<<<TT / 8, lnBlk>>>(px, ph, lg, lb);
        gemm_kernel<<<g768, 256>>>(ph, ffn_w1 + (size_t)i * C4 * CC, ffn_b1 + (size_t)i * C4,
                                   pf, CC, C4, 3, 0);
        gemm_kernel<<<g192, 256>>>(pf, ffn_w2 + (size_t)i * CC * C4, ffn_b2 + (size_t)i * CC,
                                   px, C4, CC, 0, 1);
    }

    final_kernel<<<TT / 8, lnBlk>>>(px, pw_w, pw_b, out);
}

// round 9
// speedup vs baseline: 1.3920x; 1.3912x over previous
#include <cuda_runtime.h>
#include <math.h>

// ---------------- problem constants ----------------
#define BB 2
#define SS 64
#define LL 256
#define CC 192
#define C4 768
#define HH 4
#define DH 48
#define TT (BB*SS*LL)      // 32768 tokens
#define NBLK 6

// ---------------- scratch ----------------
__device__ float g_x[TT*CC];
__device__ float g_h[TT*CC];
__device__ float g_q[TT*CC];
__device__ float g_k[TT*CC];
__device__ float g_v[TT*CC];
__device__ float g_f1[TT*C4];

__device__ __forceinline__ float elu1(float v) { return v > 0.0f ? v + 1.0f : expf(v); }
__device__ __forceinline__ float gelu_exact(float v) {
    return 0.5f * v * (1.0f + erff(v * 0.70710678118654752f));
}

// ============================================================
// Kernel 1: embed + proj + rotary
// ============================================================
__global__ void embed_kernel(const int* __restrict__ tokens,
                             const float* __restrict__ emb,
                             const float* __restrict__ pw,
                             const float* __restrict__ pb,
                             float* __restrict__ out) {
    int t = blockIdx.x;
    int c = threadIdx.x;
    __shared__ float e[64];
    __shared__ float xv[CC];
    __shared__ float invf[96];
    if (c < 64) e[c] = emb[tokens[t] * 64 + c];
    if (c >= 64 && c < 160) {
        int j = c - 64;
        invf[j] = powf(10000.0f, -(float)j / 96.0f);
    }
    __syncthreads();
    float s = pb[c];
    const float* wr = pw + c * 64;
    #pragma unroll
    for (int i = 0; i < 64; i++) s += e[i] * wr[i];
    xv[c] = s;
    __syncthreads();
    int l = t & (LL - 1);
    int c2 = (c < 96) ? c : c - 96;
    float a = (float)l * invf[c2];
    float cs = cosf(a), sn = sinf(a);
    float rot = (c < 96) ? -xv[c + 96] : xv[c - 96];
    out[(size_t)t * CC + c] = s * cs + rot * sn;
}

// ============================================================
// Kernel 2: LayerNorm over channels
// ============================================================
__global__ void ln_kernel(const float* __restrict__ x, float* __restrict__ h,
                          const float* __restrict__ g, const float* __restrict__ b) {
    int t = blockIdx.x * 8 + threadIdx.y;
    int lane = threadIdx.x;
    const float* xr = x + (size_t)t * CC;
    float v[6];
    float s = 0.f, ss = 0.f;
    #pragma unroll
    for (int i = 0; i < 6; i++) {
        v[i] = xr[lane + i * 32];
        s += v[i]; ss += v[i] * v[i];
    }
    #pragma unroll
    for (int o = 16; o; o >>= 1) {
        s  += __shfl_xor_sync(0xffffffffu, s, o);
        ss += __shfl_xor_sync(0xffffffffu, ss, o);
    }
    float m   = s * (1.0f / CC);
    float var = ss * (1.0f / CC) - m * m;
    float r   = rsqrtf(var + 1e-5f);
    float* hr = h + (size_t)t * CC;
    #pragma unroll
    for (int i = 0; i < 6; i++) {
        int c = lane + i * 32;
        hr[c] = (v[i] - m) * r * g[c] + b[c];
    }
}

// ============================================================
// TF32 tensor-core GEMM body, fragment-major shared layout.
// ============================================================
#define BM 128
#define BN 64
#define BK 16

__device__ __forceinline__ void gemm_body(
        const float* __restrict__ A, const float* __restrict__ W,
        const float* __restrict__ bias, float* __restrict__ Cout,
        int K, int N, int act, int accFlag, int rowBlk, int colBlk,
        float* As, float* Bs) {
    int tid  = threadIdx.x;
    int lane = tid & 31;
    int warp = tid >> 5;
    int warpM = warp >> 1;
    int warpN = warp & 1;
    int gid = lane >> 2;
    int tig = lane & 3;
    int row0 = rowBlk * BM;
    int col0 = colBlk * BN;

    float acc[2][4][4];
    #pragma unroll
    for (int i = 0; i < 2; i++)
        #pragma unroll
        for (int j = 0; j < 4; j++)
            #pragma unroll
            for (int q = 0; q < 4; q++) acc[i][j][q] = 0.f;

    float4 aPre[2]; float4 bPre;
    {
        #pragma unroll
        for (int i = 0; i < 2; i++) {
            int lin = tid + i * 256;
            int m  = lin >> 2;
            int kq = (lin & 3) << 2;
            aPre[i] = *(const float4*)&A[(size_t)(row0 + m) * K + kq];
        }
        int n  = tid >> 2;
        int kq = (tid & 3) << 2;
        bPre = *(const float4*)&W[(size_t)(col0 + n) * K + kq];
    }

    for (int k0 = 0; k0 < K; k0 += BK) {
        #pragma unroll
        for (int i = 0; i < 2; i++) {
            int lin = tid + i * 256;
            int m  = lin >> 2;
            int kq = (lin & 3) << 2;
            int mtile = m >> 4, r = m & 15;
            float fv[4] = {aPre[i].x, aPre[i].y, aPre[i].z, aPre[i].w};
            #pragma unroll
            for (int j = 0; j < 4; j++) {
                int k = kq + j;
                int ktile = k >> 3, kk = k & 7;
                int idx = (((mtile * 2 + ktile) * 32) + (r & 7) * 4 + (kk & 3)) * 4
                          + (r >> 3) + ((kk >> 2) << 1);
                As[idx] = fv[j];
            }
        }
        {
            int n  = tid >> 2;
            int kq = (tid & 3) << 2;
            int ntile = n >> 3, c = n & 7;
            float fv[4] = {bPre.x, bPre.y, bPre.z, bPre.w};
            #pragma unroll
            for (int j = 0; j < 4; j++) {
                int k = kq + j;
                int ktile = k >> 3, kk = k & 7;
                int idx = (((ntile * 2 + ktile) * 32) + c * 4 + (kk & 3)) * 2 + (kk >> 2);
                Bs[idx] = fv[j];
            }
        }
        __syncthreads();

        if (k0 + BK < K) {
            #pragma unroll
            for (int i = 0; i < 2; i++) {
                int lin = tid + i * 256;
                int m  = lin >> 2;
                int kq = (lin & 3) << 2;
                aPre[i] = *(const float4*)&A[(size_t)(row0 + m) * K + k0 + BK + kq];
            }
            int n  = tid >> 2;
            int kq = (tid & 3) << 2;
            bPre = *(const float4*)&W[(size_t)(col0 + n) * K + k0 + BK + kq];
        }

        #pragma unroll
        for (int ktile = 0; ktile < 2; ktile++) {
            float4 af[2]; float2 bf[4];
            #pragma unroll
            for (int mt = 0; mt < 2; mt++) {
                int mtile = warpM * 2 + mt;
                af[mt] = ((const float4*)As)[(mtile * 2 + ktile) * 32 + lane];
            }
            #pragma unroll
            for (int nt = 0; nt < 4; nt++) {
                int ntile = warpN * 4 + nt;
                bf[nt] = ((const float2*)Bs)[(ntile * 2 + ktile) * 32 + lane];
            }
            #pragma unroll
            for (int mt = 0; mt < 2; mt++)
                #pragma unroll
                for (int nt = 0; nt < 4; nt++) {
                    asm volatile(
                        "mma.sync.aligned.m16n8k8.row.col.f32.tf32.tf32.f32 "
                        "{%0,%1,%2,%3}, {%4,%5,%6,%7}, {%8,%9}, {%0,%1,%2,%3};"
                        : "+f"(acc[mt][nt][0]), "+f"(acc[mt][nt][1]),
                          "+f"(acc[mt][nt][2]), "+f"(acc[mt][nt][3])
                        : "r"(__float_as_uint(af[mt].x)), "r"(__float_as_uint(af[mt].y)),
                          "r"(__float_as_uint(af[mt].z)), "r"(__float_as_uint(af[mt].w)),
                          "r"(__float_as_uint(bf[nt].x)), "r"(__float_as_uint(bf[nt].y)));
                }
        }
        __syncthreads();
    }

    #pragma unroll
    for (int mt = 0; mt < 2; mt++) {
        int r0 = row0 + warpM * 32 + mt * 16 + gid;
        #pragma unroll
        for (int nt = 0; nt < 4; nt++) {
            int c0 = col0 + warpN * 32 + nt * 8 + tig * 2;
            #pragma unroll
            for (int half = 0; half < 2; half++) {
                int r = r0 + half * 8;
                #pragma unroll
                for (int q = 0; q < 2; q++) {
                    int c = c0 + q;
                    float v = acc[mt][nt][half * 2 + q] + bias[c];
                    if (act == 1)      v = elu1(v) * 0.14433756729740643f;
                    else if (act == 2) v = elu1(v);
                    else if (act == 3) v = gelu_exact(v);
                    size_t idx = (size_t)r * N + c;
                    if (accFlag) v += Cout[idx];
                    Cout[idx] = v;
                }
            }
        }
    }
}

__global__ __launch_bounds__(256) void gemm_kernel(
        const float* __restrict__ A, const float* __restrict__ W,
        const float* __restrict__ bias, float* __restrict__ Cout,
        int K, int N, int act, int accFlag) {
    __shared__ float As[BM * BK];
    __shared__ float Bs[BN * BK];
    gemm_body(A, W, bias, Cout, K, N, act, accFlag, blockIdx.x, blockIdx.y, As, Bs);
}

__global__ __launch_bounds__(256) void qkv_kernel(
        const float* __restrict__ A,
        const float* __restrict__ wq, const float* __restrict__ wk, const float* __restrict__ wv,
        const float* __restrict__ bq, const float* __restrict__ bk, const float* __restrict__ bv,
        float* __restrict__ oq, float* __restrict__ ok, float* __restrict__ ov) {
    __shared__ float As[BM * BK];
    __shared__ float Bs[BN * BK];
    int sel = blockIdx.y / 3;
    int cb  = blockIdx.y % 3;
    const float* W  = sel == 0 ? wq : (sel == 1 ? wk : wv);
    const float* bi = sel == 0 ? bq : (sel == 1 ? bk : bv);
    float* Cout     = sel == 0 ? oq : (sel == 1 ? ok : ov);
    int act         = sel == 0 ? 1  : (sel == 1 ? 2  : 0);
    gemm_body(A, W, bi, Cout, CC, CC, act, 0, blockIdx.x, cb, As, Bs);
}

// ============================================================
// Kernel 4: linear attention, phase-decomposed, low register count.
// Block = (group, head). smem: qs,ks,vs [N*48], kv[48*48], psum[4*48],
// ksum[48], z[N].
// kv phase: per-thread 2d x 8e outer-product tile (144 active threads).
// out phase: per-thread 2n x 8e tile over items (N/2)*6.
// ============================================================
__global__ void attn_kernel(
        const float* __restrict__ q, const float* __restrict__ k,
        const float* __restrict__ v, float* __restrict__ o,
        int N, int isCol) {
    extern __shared__ float sm[];
    float* qs   = sm;                    // N*48
    float* ks   = qs + N * DH;           // N*48
    float* vs   = ks + N * DH;           // N*48
    float* kv   = vs + N * DH;           // 48*48
    float* psum = kv + DH * DH;          // 4*48
    float* ksum = psum + 4 * DH;         // 48
    float* zz   = ksum + DH;             // N
    int g = blockIdx.x, h = blockIdx.y;
    int tid = threadIdx.x;
    int T = blockDim.x;

    // ---- phase 0: stage q,k,v ----
    for (int lin = tid; lin < N * 12; lin += T) {
        int n = lin / 12;
        int j = lin - n * 12;
        int t = isCol ? ((((g >> 8) * SS + n) << 8) + (g & 255)) : g * N + n;
        size_t base = (size_t)t * CC + h * DH + j * 4;
        ((float4*)qs)[lin] = *(const float4*)(q + base);
        ((float4*)ks)[lin] = *(const float4*)(k + base);
        ((float4*)vs)[lin] = *(const float4*)(v + base);
    }
    __syncthreads();

    // ---- phase 1a: ksum partials (4 chunks) ----
    int nq = N >> 2;
    for (int idx = tid; idx < DH * 4; idx += T) {
        int d  = idx % DH;
        int ch = idx / DH;
        int n0 = ch * nq;
        float s = 0.f;
        for (int n = n0; n < n0 + nq; n++) s += ks[n * DH + d];
        psum[ch * DH + d] = s;
    }
    // ---- phase 1b: kv = k^T v, 2d x 8e tiles ----
    if (tid < 144) {
        int dp = tid / 6, eo = tid % 6;
        int d0 = dp * 2;
        int j0 = eo * 2;                  // float4 col index base (e0 = eo*8)
        float a0[8], a1[8];
        #pragma unroll
        for (int i = 0; i < 8; i++) { a0[i] = 0.f; a1[i] = 0.f; }
        for (int n = 0; n < N; n++) {
            float k0 = ks[n * DH + d0];
            float k1 = ks[n * DH + d0 + 1];
            float4 va = ((const float4*)vs)[n * 12 + j0];
            float4 vb = ((const float4*)vs)[n * 12 + j0 + 1];
            float vv[8] = {va.x, va.y, va.z, va.w, vb.x, vb.y, vb.z, vb.w};
            #pragma unroll
            for (int i = 0; i < 8; i++) { a0[i] += k0 * vv[i]; a1[i] += k1 * vv[i]; }
        }
        ((float4*)kv)[d0 * 12 + j0]           = make_float4(a0[0], a0[1], a0[2], a0[3]);
        ((float4*)kv)[d0 * 12 + j0 + 1]       = make_float4(a0[4], a0[5], a0[6], a0[7]);
        ((float4*)kv)[(d0 + 1) * 12 + j0]     = make_float4(a1[0], a1[1], a1[2], a1[3]);
        ((float4*)kv)[(d0 + 1) * 12 + j0 + 1] = make_float4(a1[4], a1[5], a1[6], a1[7]);
    }
    __syncthreads();

    // ---- phase 2: reduce ksum ----
    if (tid < DH)
        ksum[tid] = psum[tid] + psum[DH + tid] + psum[2 * DH + tid] + psum[3 * DH + tid];
    __syncthreads();

    // ---- phase 3a: z[n] = 1/(q.ksum + eps) ----
    for (int n = tid; n < N; n += T) {
        float s = 0.f;
        #pragma unroll 8
        for (int d = 0; d < DH; d++) s += qs[n * DH + d] * ksum[d];
        zz[n] = 1.0f / (s + 1e-6f);
    }
    __syncthreads();

    // ---- phase 3b: o = (q @ kv) * z, 2n x 8e tiles ----
    int items = (N >> 1) * 6;
    for (int item = tid; item < items; item += T) {
        int np = item / 6, eo = item % 6;
        int n0 = np * 2, n1 = n0 + 1;
        int j0 = eo * 2;
        float a0[8], a1[8];
        #pragma unroll
        for (int i = 0; i < 8; i++) { a0[i] = 0.f; a1[i] = 0.f; }
        for (int d = 0; d < DH; d++) {
            float q0 = qs[n0 * DH + d];
            float q1 = qs[n1 * DH + d];
            float4 ka = ((const float4*)kv)[d * 12 + j0];
            float4 kb = ((const float4*)kv)[d * 12 + j0 + 1];
            float kk[8] = {ka.x, ka.y, ka.z, ka.w, kb.x, kb.y, kb.z, kb.w};
            #pragma unroll
            for (int i = 0; i < 8; i++) { a0[i] += q0 * kk[i]; a1[i] += q1 * kk[i]; }
        }
        float z0 = zz[n0], z1 = zz[n1];
        int t0 = isCol ? ((((g >> 8) * SS + n0) << 8) + (g & 255)) : g * N + n0;
        int t1 = isCol ? ((((g >> 8) * SS + n1) << 8) + (g & 255)) : g * N + n1;
        size_t b0 = (size_t)t0 * CC + h * DH + eo * 8;
        size_t b1 = (size_t)t1 * CC + h * DH + eo * 8;
        *(float4*)(o + b0)     = make_float4(a0[0]*z0, a0[1]*z0, a0[2]*z0, a0[3]*z0);
        *(float4*)(o + b0 + 4) = make_float4(a0[4]*z0, a0[5]*z0, a0[6]*z0, a0[7]*z0);
        *(float4*)(o + b1)     = make_float4(a1[0]*z1, a1[1]*z1, a1[2]*z1, a1[3]*z1);
        *(float4*)(o + b1 + 4) = make_float4(a1[4]*z1, a1[5]*z1, a1[6]*z1, a1[7]*z1);
    }
}

// ============================================================
// Kernel 5: head
// ============================================================
__global__ void final_kernel(const float* __restrict__ x,
                             const float* __restrict__ pw,
                             const float* __restrict__ pb,
                             float* __restrict__ out) {
    int t = blockIdx.x * 8 + threadIdx.y;
    int lane = threadIdx.x;
    const float* xr = x + (size_t)t * CC;
    float s = 0.f;
    #pragma unroll
    for (int i = 0; i < 6; i++) {
        int c = lane + i * 32;
        s += xr[c] * pw[c];
    }
    #pragma unroll
    for (int o = 16; o; o >>= 1) s += __shfl_xor_sync(0xffffffffu, s, o);
    if (lane == 0) {
        float ov = s + pb[0];
        float sp = (ov > 20.f) ? ov : log1pf(expf(ov));
        out[t] = 1.0f / (1.0f + expf(-sp));
    }
}

// ============================================================
// Host orchestration
// ============================================================
extern "C" void kernel_launch(void* const* d_in, const int* in_sizes, int n_in,
                              void* d_out, int out_size) {
    const int*   tokens = (const int*)  d_in[0];
    const float* emb    = (const float*)d_in[1];
    const float* proj_w = (const float*)d_in[2];
    const float* proj_b = (const float*)d_in[3];
    const float* ln_g   = (const float*)d_in[4];
    const float* ln_b   = (const float*)d_in[5];
    const float* wq     = (const float*)d_in[6];
    const float* wk     = (const float*)d_in[7];
    const float* wv     = (const float*)d_in[8];
    const float* wo     = (const float*)d_in[9];
    const float* bq     = (const float*)d_in[10];
    const float* bk     = (const float*)d_in[11];
    const float* bv     = (const float*)d_in[12];
    const float* bo     = (const float*)d_in[13];
    const float* ffn_w1 = (const float*)d_in[14];
    const float* ffn_b1 = (const float*)d_in[15];
    const float* ffn_w2 = (const float*)d_in[16];
    const float* ffn_b2 = (const float*)d_in[17];
    const float* pw_w   = (const float*)d_in[18];
    const float* pw_b   = (const float*)d_in[19];
    float* out = (float*)d_out;

    float *px, *ph, *pq, *pk, *pv, *pf;
    cudaGetSymbolAddress((void**)&px, g_x);
    cudaGetSymbolAddress((void**)&ph, g_h);
    cudaGetSymbolAddress((void**)&pq, g_q);
    cudaGetSymbolAddress((void**)&pk, g_k);
    cudaGetSymbolAddress((void**)&pv, g_v);
    cudaGetSymbolAddress((void**)&pf, g_f1);

    // dynamic smem: floats = 3*N*48 + 48*48 + 4*48 + 48 + N
    size_t smemRow = (size_t)(3 * LL * DH + DH * DH + 5 * DH + LL) * sizeof(float); // 158656
    size_t smemCol = (size_t)(3 * SS * DH + DH * DH + 5 * DH + SS) * sizeof(float); // 47296
    cudaFuncSetAttribute(attn_kernel, cudaFuncAttributeMaxDynamicSharedMemorySize, 163840);

    dim3 lnBlk(32, 8);
    dim3 gQKV(TT / BM, 9);
    dim3 g192(TT / BM, CC / BN);
    dim3 g768(TT / BM, C4 / BN);

    embed_kernel<<<TT, CC>>>(tokens, emb, proj_w, proj_b, px);

    for (int i = 0; i < NBLK; i++) {
        for (int dir = 0; dir < 2; dir++) {
            const float* lg = ln_g + (size_t)(i * 3 + dir) * CC;
            const float* lb = ln_b + (size_t)(i * 3 + dir) * CC;
            ln_kernel<<<TT / 8, lnBlk>>>(px, ph, lg, lb);

            size_t woff = ((size_t)i * 2 + dir) * CC * CC;
            size_t boff = ((size_t)i * 2 + dir) * CC;
            qkv_kernel<<<gQKV, 256>>>(ph, wq + woff, wk + woff, wv + woff,
                                      bq + boff, bk + boff, bv + boff, pq, pk, pv);

            if (dir == 0) {
                attn_kernel<<<dim3(BB * SS, HH), 512, smemRow>>>(pq, pk, pv, ph, LL, 0);
            } else {
                attn_kernel<<<dim3(BB * LL, HH), 256, smemCol>>>(pq, pk, pv, ph, SS, 1);
            }

            gemm_kernel<<<g192, 256>>>(ph, wo + woff, bo + boff, px, CC, CC, 0, 1);
        }
        const float* lg = ln_g + (size_t)(i * 3 + 2) * CC;
        const float* lb = ln_b + (size_t)(i * 3 + 2) * CC;
        ln_kernel<<<TT / 8, lnBlk>>>(px, ph, lg, lb);
        gemm_kernel<<<g768, 256>>>(ph, ffn_w1 + (size_t)i * C4 * CC, ffn_b1 + (size_t)i * C4,
                                   pf, CC, C4, 3, 0);
        gemm_kernel<<<g192, 256>>>(pf, ffn_w2 + (size_t)i * CC * C4, ffn_b2 + (size_t)i * CC,
                                   px, C4, CC, 0, 1);
    }

    final_kernel<<<TT / 8, lnBlk>>>(px, pw_w, pw_b, out);
}

// round 10
// speedup vs baseline: 1.4221x; 1.0216x over previous
#include <cuda_runtime.h>
#include <math.h>

// ---------------- problem constants ----------------
#define BB 2
#define SS 64
#define LL 256
#define CC 192
#define C4 768
#define HH 4
#define DH 48
#define TT (BB*SS*LL)      // 32768 tokens
#define NBLK 6

// ---------------- scratch ----------------
__device__ float g_x[TT*CC];
__device__ float g_h[TT*CC];
__device__ float g_q[TT*CC];
__device__ float g_k[TT*CC];
__device__ float g_v[TT*CC];
__device__ float g_f1[TT*C4];

__device__ __forceinline__ float elu1(float v) { return v > 0.0f ? v + 1.0f : expf(v); }
__device__ __forceinline__ float gelu_exact(float v) {
    return 0.5f * v * (1.0f + erff(v * 0.70710678118654752f));
}

// ============================================================
// Kernel 1: embed + proj + rotary
// ============================================================
__global__ void embed_kernel(const int* __restrict__ tokens,
                             const float* __restrict__ emb,
                             const float* __restrict__ pw,
                             const float* __restrict__ pb,
                             float* __restrict__ out) {
    int t = blockIdx.x;
    int c = threadIdx.x;
    __shared__ float e[64];
    __shared__ float xv[CC];
    __shared__ float invf[96];
    if (c < 64) e[c] = emb[tokens[t] * 64 + c];
    if (c >= 64 && c < 160) {
        int j = c - 64;
        invf[j] = powf(10000.0f, -(float)j / 96.0f);
    }
    __syncthreads();
    float s = pb[c];
    const float* wr = pw + c * 64;
    #pragma unroll
    for (int i = 0; i < 64; i++) s += e[i] * wr[i];
    xv[c] = s;
    __syncthreads();
    int l = t & (LL - 1);
    int c2 = (c < 96) ? c : c - 96;
    float a = (float)l * invf[c2];
    float cs = cosf(a), sn = sinf(a);
    float rot = (c < 96) ? -xv[c + 96] : xv[c - 96];
    out[(size_t)t * CC + c] = s * cs + rot * sn;
}

// ============================================================
// Kernel 2: LayerNorm over channels
// ============================================================
__global__ void ln_kernel(const float* __restrict__ x, float* __restrict__ h,
                          const float* __restrict__ g, const float* __restrict__ b) {
    int t = blockIdx.x * 8 + threadIdx.y;
    int lane = threadIdx.x;
    const float* xr = x + (size_t)t * CC;
    float v[6];
    float s = 0.f, ss = 0.f;
    #pragma unroll
    for (int i = 0; i < 6; i++) {
        v[i] = xr[lane + i * 32];
        s += v[i]; ss += v[i] * v[i];
    }
    #pragma unroll
    for (int o = 16; o; o >>= 1) {
        s  += __shfl_xor_sync(0xffffffffu, s, o);
        ss += __shfl_xor_sync(0xffffffffu, ss, o);
    }
    float m   = s * (1.0f / CC);
    float var = ss * (1.0f / CC) - m * m;
    float r   = rsqrtf(var + 1e-5f);
    float* hr = h + (size_t)t * CC;
    #pragma unroll
    for (int i = 0; i < 6; i++) {
        int c = lane + i * 32;
        hr[c] = (v[i] - m) * r * g[c] + b[c];
    }
}

// ============================================================
// TF32 tensor-core GEMM, fragment-major shared layout,
// 2-stage ping-pong pipeline: ONE __syncthreads per k-tile.
//   iter i: ldg(next) -> compute(buf i%2) -> store(buf (i+1)%2) -> sync
// (writing (i+1)%2 is safe: its readers finished in iter i-1, drained
//  by the barrier at end of iter i-1)
// ============================================================
#define BM 128
#define BN 64
#define BK 16
#define ASZ (BM*BK)
#define BSZ (BN*BK)

__device__ __forceinline__ void gemm_stage(
        float* As, float* Bs, const float4 aPre[2], const float4 bPre,
        int tid) {
    #pragma unroll
    for (int i = 0; i < 2; i++) {
        int lin = tid + i * 256;
        int m  = lin >> 2;
        int kq = (lin & 3) << 2;
        int mtile = m >> 4, r = m & 15;
        float fv[4] = {aPre[i].x, aPre[i].y, aPre[i].z, aPre[i].w};
        #pragma unroll
        for (int j = 0; j < 4; j++) {
            int k = kq + j;
            int ktile = k >> 3, kk = k & 7;
            int idx = (((mtile * 2 + ktile) * 32) + (r & 7) * 4 + (kk & 3)) * 4
                      + (r >> 3) + ((kk >> 2) << 1);
            As[idx] = fv[j];
        }
    }
    {
        int n  = tid >> 2;
        int kq = (tid & 3) << 2;
        int ntile = n >> 3, c = n & 7;
        float fv[4] = {bPre.x, bPre.y, bPre.z, bPre.w};
        #pragma unroll
        for (int j = 0; j < 4; j++) {
            int k = kq + j;
            int ktile = k >> 3, kk = k & 7;
            int idx = (((ntile * 2 + ktile) * 32) + c * 4 + (kk & 3)) * 2 + (kk >> 2);
            Bs[idx] = fv[j];
        }
    }
}

__device__ __forceinline__ void gemm_body(
        const float* __restrict__ A, const float* __restrict__ W,
        const float* __restrict__ bias, float* __restrict__ Cout,
        int K, int N, int act, int accFlag, int rowBlk, int colBlk,
        float* AsBuf, float* BsBuf) {
    int tid  = threadIdx.x;
    int lane = tid & 31;
    int warp = tid >> 5;
    int warpM = warp >> 1;
    int warpN = warp & 1;
    int gid = lane >> 2;
    int tig = lane & 3;
    int row0 = rowBlk * BM;
    int col0 = colBlk * BN;

    float acc[2][4][4];
    #pragma unroll
    for (int i = 0; i < 2; i++)
        #pragma unroll
        for (int j = 0; j < 4; j++)
            #pragma unroll
            for (int q = 0; q < 4; q++) acc[i][j][q] = 0.f;

    // gmem addresses for this thread's staged elements
    int aM0 = (tid) >> 2,       aK = (tid & 3) << 2;
    int aM1 = (tid + 256) >> 2;
    int bN  = tid >> 2,         bK = (tid & 3) << 2;
    const float* aPtr0 = A + (size_t)(row0 + aM0) * K + aK;
    const float* aPtr1 = A + (size_t)(row0 + aM1) * K + aK;
    const float* bPtr  = W + (size_t)(col0 + bN) * K + bK;

    float4 aPre[2]; float4 bPre;
    aPre[0] = *(const float4*)aPtr0;
    aPre[1] = *(const float4*)aPtr1;
    bPre    = *(const float4*)bPtr;

    int NT = K / BK;
    gemm_stage(AsBuf, BsBuf, aPre, bPre, tid);   // stage 0
    __syncthreads();

    for (int it = 0; it < NT; it++) {
        int cur = it & 1;
        // prefetch next tile into regs
        if (it + 1 < NT) {
            int off = (it + 1) * BK;
            aPre[0] = *(const float4*)(aPtr0 + off);
            aPre[1] = *(const float4*)(aPtr1 + off);
            bPre    = *(const float4*)(bPtr  + off);
        }
        // compute on current buffer
        float* Ac = AsBuf + cur * ASZ;
        float* Bc = BsBuf + cur * BSZ;
        #pragma unroll
        for (int ktile = 0; ktile < 2; ktile++) {
            float4 af[2]; float2 bf[4];
            #pragma unroll
            for (int mt = 0; mt < 2; mt++) {
                int mtile = warpM * 2 + mt;
                af[mt] = ((const float4*)Ac)[(mtile * 2 + ktile) * 32 + lane];
            }
            #pragma unroll
            for (int nt = 0; nt < 4; nt++) {
                int ntile = warpN * 4 + nt;
                bf[nt] = ((const float2*)Bc)[(ntile * 2 + ktile) * 32 + lane];
            }
            #pragma unroll
            for (int mt = 0; mt < 2; mt++)
                #pragma unroll
                for (int nt = 0; nt < 4; nt++) {
                    asm volatile(
                        "mma.sync.aligned.m16n8k8.row.col.f32.tf32.tf32.f32 "
                        "{%0,%1,%2,%3}, {%4,%5,%6,%7}, {%8,%9}, {%0,%1,%2,%3};"
                        : "+f"(acc[mt][nt][0]), "+f"(acc[mt][nt][1]),
                          "+f"(acc[mt][nt][2]), "+f"(acc[mt][nt][3])
                        : "r"(__float_as_uint(af[mt].x)), "r"(__float_as_uint(af[mt].y)),
                          "r"(__float_as_uint(af[mt].z)), "r"(__float_as_uint(af[mt].w)),
                          "r"(__float_as_uint(bf[nt].x)), "r"(__float_as_uint(bf[nt].y)));
                }
        }
        // stage next tile into the other buffer (safe: last read in it-1)
        if (it + 1 < NT) {
            gemm_stage(AsBuf + (cur ^ 1) * ASZ, BsBuf + (cur ^ 1) * BSZ, aPre, bPre, tid);
            __syncthreads();
        }
    }

    #pragma unroll
    for (int mt = 0; mt < 2; mt++) {
        int r0 = row0 + warpM * 32 + mt * 16 + gid;
        #pragma unroll
        for (int nt = 0; nt < 4; nt++) {
            int c0 = col0 + warpN * 32 + nt * 8 + tig * 2;
            #pragma unroll
            for (int half = 0; half < 2; half++) {
                int r = r0 + half * 8;
                #pragma unroll
                for (int q = 0; q < 2; q++) {
                    int c = c0 + q;
                    float v = acc[mt][nt][half * 2 + q] + bias[c];
                    if (act == 1)      v = elu1(v) * 0.14433756729740643f;
                    else if (act == 2) v = elu1(v);
                    else if (act == 3) v = gelu_exact(v);
                    size_t idx = (size_t)r * N + c;
                    if (accFlag) v += Cout[idx];
                    Cout[idx] = v;
                }
            }
        }
    }
}

__global__ __launch_bounds__(256) void gemm_kernel(
        const float* __restrict__ A, const float* __restrict__ W,
        const float* __restrict__ bias, float* __restrict__ Cout,
        int K, int N, int act, int accFlag) {
    __shared__ float As[2 * ASZ];
    __shared__ float Bs[2 * BSZ];
    gemm_body(A, W, bias, Cout, K, N, act, accFlag, blockIdx.x, blockIdx.y, As, Bs);
}

__global__ __launch_bounds__(256) void qkv_kernel(
        const float* __restrict__ A,
        const float* __restrict__ wq, const float* __restrict__ wk, const float* __restrict__ wv,
        const float* __restrict__ bq, const float* __restrict__ bk, const float* __restrict__ bv,
        float* __restrict__ oq, float* __restrict__ ok, float* __restrict__ ov) {
    __shared__ float As[2 * ASZ];
    __shared__ float Bs[2 * BSZ];
    int sel = blockIdx.y / 3;
    int cb  = blockIdx.y % 3;
    const float* W  = sel == 0 ? wq : (sel == 1 ? wk : wv);
    const float* bi = sel == 0 ? bq : (sel == 1 ? bk : bv);
    float* Cout     = sel == 0 ? oq : (sel == 1 ? ok : ov);
    int act         = sel == 0 ? 1  : (sel == 1 ? 2  : 0);
    gemm_body(A, W, bi, Cout, CC, CC, act, 0, blockIdx.x, cb, As, Bs);
}

// ============================================================
// Kernel 4: linear attention, phase-decomposed (unchanged from R9 win)
// ============================================================
__global__ void attn_kernel(
        const float* __restrict__ q, const float* __restrict__ k,
        const float* __restrict__ v, float* __restrict__ o,
        int N, int isCol) {
    extern __shared__ float sm[];
    float* qs   = sm;                    // N*48
    float* ks   = qs + N * DH;           // N*48
    float* vs   = ks + N * DH;           // N*48
    float* kv   = vs + N * DH;           // 48*48
    float* psum = kv + DH * DH;          // 4*48
    float* ksum = psum + 4 * DH;         // 48
    float* zz   = ksum + DH;             // N
    int g = blockIdx.x, h = blockIdx.y;
    int tid = threadIdx.x;
    int T = blockDim.x;

    for (int lin = tid; lin < N * 12; lin += T) {
        int n = lin / 12;
        int j = lin - n * 12;
        int t = isCol ? ((((g >> 8) * SS + n) << 8) + (g & 255)) : g * N + n;
        size_t base = (size_t)t * CC + h * DH + j * 4;
        ((float4*)qs)[lin] = *(const float4*)(q + base);
        ((float4*)ks)[lin] = *(const float4*)(k + base);
        ((float4*)vs)[lin] = *(const float4*)(v + base);
    }
    __syncthreads();

    int nq = N >> 2;
    for (int idx = tid; idx < DH * 4; idx += T) {
        int d  = idx % DH;
        int ch = idx / DH;
        int n0 = ch * nq;
        float s = 0.f;
        for (int n = n0; n < n0 + nq; n++) s += ks[n * DH + d];
        psum[ch * DH + d] = s;
    }
    if (tid < 144) {
        int dp = tid / 6, eo = tid % 6;
        int d0 = dp * 2;
        int j0 = eo * 2;
        float a0[8], a1[8];
        #pragma unroll
        for (int i = 0; i < 8; i++) { a0[i] = 0.f; a1[i] = 0.f; }
        for (int n = 0; n < N; n++) {
            float k0 = ks[n * DH + d0];
            float k1 = ks[n * DH + d0 + 1];
            float4 va = ((const float4*)vs)[n * 12 + j0];
            float4 vb = ((const float4*)vs)[n * 12 + j0 + 1];
            float vv[8] = {va.x, va.y, va.z, va.w, vb.x, vb.y, vb.z, vb.w};
            #pragma unroll
            for (int i = 0; i < 8; i++) { a0[i] += k0 * vv[i]; a1[i] += k1 * vv[i]; }
        }
        ((float4*)kv)[d0 * 12 + j0]           = make_float4(a0[0], a0[1], a0[2], a0[3]);
        ((float4*)kv)[d0 * 12 + j0 + 1]       = make_float4(a0[4], a0[5], a0[6], a0[7]);
        ((float4*)kv)[(d0 + 1) * 12 + j0]     = make_float4(a1[0], a1[1], a1[2], a1[3]);
        ((float4*)kv)[(d0 + 1) * 12 + j0 + 1] = make_float4(a1[4], a1[5], a1[6], a1[7]);
    }
    __syncthreads();

    if (tid < DH)
        ksum[tid] = psum[tid] + psum[DH + tid] + psum[2 * DH + tid] + psum[3 * DH + tid];
    __syncthreads();

    for (int n = tid; n < N; n += T) {
        float s = 0.f;
        #pragma unroll 8
        for (int d = 0; d < DH; d++) s += qs[n * DH + d] * ksum[d];
        zz[n] = 1.0f / (s + 1e-6f);
    }
    __syncthreads();

    int items = (N >> 1) * 6;
    for (int item = tid; item < items; item += T) {
        int np = item / 6, eo = item % 6;
        int n0 = np * 2, n1 = n0 + 1;
        int j0 = eo * 2;
        float a0[8], a1[8];
        #pragma unroll
        for (int i = 0; i < 8; i++) { a0[i] = 0.f; a1[i] = 0.f; }
        for (int d = 0; d < DH; d++) {
            float q0 = qs[n0 * DH + d];
            float q1 = qs[n1 * DH + d];
            float4 ka = ((const float4*)kv)[d * 12 + j0];
            float4 kb = ((const float4*)kv)[d * 12 + j0 + 1];
            float kk[8] = {ka.x, ka.y, ka.z, ka.w, kb.x, kb.y, kb.z, kb.w};
            #pragma unroll
            for (int i = 0; i < 8; i++) { a0[i] += q0 * kk[i]; a1[i] += q1 * kk[i]; }
        }
        float z0 = zz[n0], z1 = zz[n1];
        int t0 = isCol ? ((((g >> 8) * SS + n0) << 8) + (g & 255)) : g * N + n0;
        int t1 = isCol ? ((((g >> 8) * SS + n1) << 8) + (g & 255)) : g * N + n1;
        size_t b0 = (size_t)t0 * CC + h * DH + eo * 8;
        size_t b1 = (size_t)t1 * CC + h * DH + eo * 8;
        *(float4*)(o + b0)     = make_float4(a0[0]*z0, a0[1]*z0, a0[2]*z0, a0[3]*z0);
        *(float4*)(o + b0 + 4) = make_float4(a0[4]*z0, a0[5]*z0, a0[6]*z0, a0[7]*z0);
        *(float4*)(o + b1)     = make_float4(a1[0]*z1, a1[1]*z1, a1[2]*z1, a1[3]*z1);
        *(float4*)(o + b1 + 4) = make_float4(a1[4]*z1, a1[5]*z1, a1[6]*z1, a1[7]*z1);
    }
}

// ============================================================
// Kernel 5: head
// ============================================================
__global__ void final_kernel(const float* __restrict__ x,
                             const float* __restrict__ pw,
                             const float* __restrict__ pb,
                             float* __restrict__ out) {
    int t = blockIdx.x * 8 + threadIdx.y;
    int lane = threadIdx.x;
    const float* xr = x + (size_t)t * CC;
    float s = 0.f;
    #pragma unroll
    for (int i = 0; i < 6; i++) {
        int c = lane + i * 32;
        s += xr[c] * pw[c];
    }
    #pragma unroll
    for (int o = 16; o; o >>= 1) s += __shfl_xor_sync(0xffffffffu, s, o);
    if (lane == 0) {
        float ov = s + pb[0];
        float sp = (ov > 20.f) ? ov : log1pf(expf(ov));
        out[t] = 1.0f / (1.0f + expf(-sp));
    }
}

// ============================================================
// Host orchestration
// ============================================================
extern "C" void kernel_launch(void* const* d_in, const int* in_sizes, int n_in,
                              void* d_out, int out_size) {
    const int*   tokens = (const int*)  d_in[0];
    const float* emb    = (const float*)d_in[1];
    const float* proj_w = (const float*)d_in[2];
    const float* proj_b = (const float*)d_in[3];
    const float* ln_g   = (const float*)d_in[4];
    const float* ln_b   = (const float*)d_in[5];
    const float* wq     = (const float*)d_in[6];
    const float* wk     = (const float*)d_in[7];
    const float* wv     = (const float*)d_in[8];
    const float* wo     = (const float*)d_in[9];
    const float* bq     = (const float*)d_in[10];
    const float* bk     = (const float*)d_in[11];
    const float* bv     = (const float*)d_in[12];
    const float* bo     = (const float*)d_in[13];
    const float* ffn_w1 = (const float*)d_in[14];
    const float* ffn_b1 = (const float*)d_in[15];
    const float* ffn_w2 = (const float*)d_in[16];
    const float* ffn_b2 = (const float*)d_in[17];
    const float* pw_w   = (const float*)d_in[18];
    const float* pw_b   = (const float*)d_in[19];
    float* out = (float*)d_out;

    float *px, *ph, *pq, *pk, *pv, *pf;
    cudaGetSymbolAddress((void**)&px, g_x);
    cudaGetSymbolAddress((void**)&ph, g_h);
    cudaGetSymbolAddress((void**)&pq, g_q);
    cudaGetSymbolAddress((void**)&pk, g_k);
    cudaGetSymbolAddress((void**)&pv, g_v);
    cudaGetSymbolAddress((void**)&pf, g_f1);

    size_t smemRow = (size_t)(3 * LL * DH + DH * DH + 5 * DH + LL) * sizeof(float);
    size_t smemCol = (size_t)(3 * SS * DH + DH * DH + 5 * DH + SS) * sizeof(float);
    cudaFuncSetAttribute(attn_kernel, cudaFuncAttributeMaxDynamicSharedMemorySize, 163840);

    dim3 lnBlk(32, 8);
    dim3 gQKV(TT / BM, 9);
    dim3 g192(TT / BM, CC / BN);
    dim3 g768(TT / BM, C4 / BN);

    embed_kernel<<<TT, CC>>>(tokens, emb, proj_w, proj_b, px);

    for (int i = 0; i < NBLK; i++) {
        for (int dir = 0; dir < 2; dir++) {
            const float* lg = ln_g + (size_t)(i * 3 + dir) * CC;
            const float* lb = ln_b + (size_t)(i * 3 + dir) * CC;
            ln_kernel<<<TT / 8, lnBlk>>>(px, ph, lg, lb);

            size_t woff = ((size_t)i * 2 + dir) * CC * CC;
            size_t boff = ((size_t)i * 2 + dir) * CC;
            qkv_kernel<<<gQKV, 256>>>(ph, wq + woff, wk + woff, wv + woff,
                                      bq + boff, bk + boff, bv + boff, pq, pk, pv);

            if (dir == 0) {
                attn_kernel<<<dim3(BB * SS, HH), 512, smemRow>>>(pq, pk, pv, ph, LL, 0);
            } else {
                attn_kernel<<<dim3(BB * LL, HH), 256, smemCol>>>(pq, pk, pv, ph, SS, 1);
            }

            gemm_kernel<<<g192, 256>>>(ph, wo + woff, bo + boff, px, CC, CC, 0, 1);
        }
        const float* lg = ln_g + (size_t)(i * 3 + 2) * CC;
        const float* lb = ln_b + (size_t)(i * 3 + 2) * CC;
        ln_kernel<<<TT / 8, lnBlk>>>(px, ph, lg, lb);
        gemm_kernel<<<g768, 256>>>(ph, ffn_w1 + (size_t)i * C4 * CC, ffn_b1 + (size_t)i * C4,
                                   pf, CC, C4, 3, 0);
        gemm_kernel<<<g192, 256>>>(pf, ffn_w2 + (size_t)i * CC * C4, ffn_b2 + (size_t)i * CC,
                                   px, C4, CC, 0, 1);
    }

    final_kernel<<<TT / 8, lnBlk>>>(px, pw_w, pw_b, out);
}

// round 11
// speedup vs baseline: 1.4707x; 1.0341x over previous
#include <cuda_runtime.h>
#include <math.h>

// ---------------- problem constants ----------------
#define BB 2
#define SS 64
#define LL 256
#define CC 192
#define C4 768
#define HH 4
#define DH 48
#define TT (BB*SS*LL)      // 32768 tokens
#define NBLK 6

// ---------------- scratch ----------------
__device__ float g_x[TT*CC];
__device__ float g_h[TT*CC];
__device__ float g_q[TT*CC];
__device__ float g_k[TT*CC];
__device__ float g_v[TT*CC];
__device__ float g_f1[TT*C4];

__device__ __forceinline__ float elu1(float v) { return v > 0.0f ? v + 1.0f : expf(v); }
__device__ __forceinline__ float gelu_exact(float v) {
    return 0.5f * v * (1.0f + erff(v * 0.70710678118654752f));
}

// ============================================================
// Kernel 1: embed + proj + rotary
// ============================================================
__global__ void embed_kernel(const int* __restrict__ tokens,
                             const float* __restrict__ emb,
                             const float* __restrict__ pw,
                             const float* __restrict__ pb,
                             float* __restrict__ out) {
    int t = blockIdx.x;
    int c = threadIdx.x;
    __shared__ float e[64];
    __shared__ float xv[CC];
    __shared__ float invf[96];
    if (c < 64) e[c] = emb[tokens[t] * 64 + c];
    if (c >= 64 && c < 160) {
        int j = c - 64;
        invf[j] = powf(10000.0f, -(float)j / 96.0f);
    }
    __syncthreads();
    float s = pb[c];
    const float* wr = pw + c * 64;
    #pragma unroll
    for (int i = 0; i < 64; i++) s += e[i] * wr[i];
    xv[c] = s;
    __syncthreads();
    int l = t & (LL - 1);
    int c2 = (c < 96) ? c : c - 96;
    float a = (float)l * invf[c2];
    float cs = cosf(a), sn = sinf(a);
    float rot = (c < 96) ? -xv[c + 96] : xv[c - 96];
    out[(size_t)t * CC + c] = s * cs + rot * sn;
}

// ============================================================
// Kernel 2: LayerNorm over channels
// ============================================================
__global__ void ln_kernel(const float* __restrict__ x, float* __restrict__ h,
                          const float* __restrict__ g, const float* __restrict__ b) {
    int t = blockIdx.x * 8 + threadIdx.y;
    int lane = threadIdx.x;
    const float* xr = x + (size_t)t * CC;
    float v[6];
    float s = 0.f, ss = 0.f;
    #pragma unroll
    for (int i = 0; i < 6; i++) {
        v[i] = xr[lane + i * 32];
        s += v[i]; ss += v[i] * v[i];
    }
    #pragma unroll
    for (int o = 16; o; o >>= 1) {
        s  += __shfl_xor_sync(0xffffffffu, s, o);
        ss += __shfl_xor_sync(0xffffffffu, ss, o);
    }
    float m   = s * (1.0f / CC);
    float var = ss * (1.0f / CC) - m * m;
    float r   = rsqrtf(var + 1e-5f);
    float* hr = h + (size_t)t * CC;
    #pragma unroll
    for (int i = 0; i < 6; i++) {
        int c = lane + i * 32;
        hr[c] = (v[i] - m) * r * g[c] + b[c];
    }
}

// ============================================================
// TF32 tensor-core GEMM, fragment-major shared layout, ping-pong pipeline.
// ============================================================
#define BM 128
#define BN 64
#define BK 16
#define ASZ (BM*BK)
#define BSZ (BN*BK)

__device__ __forceinline__ void gemm_stage(
        float* As, float* Bs, const float4 aPre[2], const float4 bPre,
        int tid) {
    #pragma unroll
    for (int i = 0; i < 2; i++) {
        int lin = tid + i * 256;
        int m  = lin >> 2;
        int kq = (lin & 3) << 2;
        int mtile = m >> 4, r = m & 15;
        float fv[4] = {aPre[i].x, aPre[i].y, aPre[i].z, aPre[i].w};
        #pragma unroll
        for (int j = 0; j < 4; j++) {
            int k = kq + j;
            int ktile = k >> 3, kk = k & 7;
            int idx = (((mtile * 2 + ktile) * 32) + (r & 7) * 4 + (kk & 3)) * 4
                      + (r >> 3) + ((kk >> 2) << 1);
            As[idx] = fv[j];
        }
    }
    {
        int n  = tid >> 2;
        int kq = (tid & 3) << 2;
        int ntile = n >> 3, c = n & 7;
        float fv[4] = {bPre.x, bPre.y, bPre.z, bPre.w};
        #pragma unroll
        for (int j = 0; j < 4; j++) {
            int k = kq + j;
            int ktile = k >> 3, kk = k & 7;
            int idx = (((ntile * 2 + ktile) * 32) + c * 4 + (kk & 3)) * 2 + (kk >> 2);
            Bs[idx] = fv[j];
        }
    }
}

__device__ __forceinline__ void gemm_body(
        const float* __restrict__ A, const float* __restrict__ W,
        const float* __restrict__ bias, float* __restrict__ Cout,
        int K, int N, int act, int accFlag, int rowBlk, int colBlk,
        float* AsBuf, float* BsBuf) {
    int tid  = threadIdx.x;
    int lane = tid & 31;
    int warp = tid >> 5;
    int warpM = warp >> 1;
    int warpN = warp & 1;
    int gid = lane >> 2;
    int tig = lane & 3;
    int row0 = rowBlk * BM;
    int col0 = colBlk * BN;

    float acc[2][4][4];
    #pragma unroll
    for (int i = 0; i < 2; i++)
        #pragma unroll
        for (int j = 0; j < 4; j++)
            #pragma unroll
            for (int q = 0; q < 4; q++) acc[i][j][q] = 0.f;

    int aM0 = (tid) >> 2,       aK = (tid & 3) << 2;
    int aM1 = (tid + 256) >> 2;
    int bN  = tid >> 2,         bK = (tid & 3) << 2;
    const float* aPtr0 = A + (size_t)(row0 + aM0) * K + aK;
    const float* aPtr1 = A + (size_t)(row0 + aM1) * K + aK;
    const float* bPtr  = W + (size_t)(col0 + bN) * K + bK;

    float4 aPre[2]; float4 bPre;
    aPre[0] = *(const float4*)aPtr0;
    aPre[1] = *(const float4*)aPtr1;
    bPre    = *(const float4*)bPtr;

    int NT = K / BK;
    gemm_stage(AsBuf, BsBuf, aPre, bPre, tid);
    __syncthreads();

    for (int it = 0; it < NT; it++) {
        int cur = it & 1;
        if (it + 1 < NT) {
            int off = (it + 1) * BK;
            aPre[0] = *(const float4*)(aPtr0 + off);
            aPre[1] = *(const float4*)(aPtr1 + off);
            bPre    = *(const float4*)(bPtr  + off);
        }
        float* Ac = AsBuf + cur * ASZ;
        float* Bc = BsBuf + cur * BSZ;
        #pragma unroll
        for (int ktile = 0; ktile < 2; ktile++) {
            float4 af[2]; float2 bf[4];
            #pragma unroll
            for (int mt = 0; mt < 2; mt++) {
                int mtile = warpM * 2 + mt;
                af[mt] = ((const float4*)Ac)[(mtile * 2 + ktile) * 32 + lane];
            }
            #pragma unroll
            for (int nt = 0; nt < 4; nt++) {
                int ntile = warpN * 4 + nt;
                bf[nt] = ((const float2*)Bc)[(ntile * 2 + ktile) * 32 + lane];
            }
            #pragma unroll
            for (int mt = 0; mt < 2; mt++)
                #pragma unroll
                for (int nt = 0; nt < 4; nt++) {
                    asm volatile(
                        "mma.sync.aligned.m16n8k8.row.col.f32.tf32.tf32.f32 "
                        "{%0,%1,%2,%3}, {%4,%5,%6,%7}, {%8,%9}, {%0,%1,%2,%3};"
                        : "+f"(acc[mt][nt][0]), "+f"(acc[mt][nt][1]),
                          "+f"(acc[mt][nt][2]), "+f"(acc[mt][nt][3])
                        : "r"(__float_as_uint(af[mt].x)), "r"(__float_as_uint(af[mt].y)),
                          "r"(__float_as_uint(af[mt].z)), "r"(__float_as_uint(af[mt].w)),
                          "r"(__float_as_uint(bf[nt].x)), "r"(__float_as_uint(bf[nt].y)));
                }
        }
        if (it + 1 < NT) {
            gemm_stage(AsBuf + (cur ^ 1) * ASZ, BsBuf + (cur ^ 1) * BSZ, aPre, bPre, tid);
            __syncthreads();
        }
    }

    #pragma unroll
    for (int mt = 0; mt < 2; mt++) {
        int r0 = row0 + warpM * 32 + mt * 16 + gid;
        #pragma unroll
        for (int nt = 0; nt < 4; nt++) {
            int c0 = col0 + warpN * 32 + nt * 8 + tig * 2;
            #pragma unroll
            for (int half = 0; half < 2; half++) {
                int r = r0 + half * 8;
                #pragma unroll
                for (int q = 0; q < 2; q++) {
                    int c = c0 + q;
                    float v = acc[mt][nt][half * 2 + q] + bias[c];
                    if (act == 1)      v = elu1(v) * 0.14433756729740643f;
                    else if (act == 2) v = elu1(v);
                    else if (act == 3) v = gelu_exact(v);
                    size_t idx = (size_t)r * N + c;
                    if (accFlag) v += Cout[idx];
                    Cout[idx] = v;
                }
            }
        }
    }
}

__global__ __launch_bounds__(256) void gemm_kernel(
        const float* __restrict__ A, const float* __restrict__ W,
        const float* __restrict__ bias, float* __restrict__ Cout,
        int K, int N, int act, int accFlag) {
    __shared__ float As[2 * ASZ];
    __shared__ float Bs[2 * BSZ];
    gemm_body(A, W, bias, Cout, K, N, act, accFlag, blockIdx.x, blockIdx.y, As, Bs);
}

__global__ __launch_bounds__(256) void qkv_kernel(
        const float* __restrict__ A,
        const float* __restrict__ wq, const float* __restrict__ wk, const float* __restrict__ wv,
        const float* __restrict__ bq, const float* __restrict__ bk, const float* __restrict__ bv,
        float* __restrict__ oq, float* __restrict__ ok, float* __restrict__ ov) {
    __shared__ float As[2 * ASZ];
    __shared__ float Bs[2 * BSZ];
    int sel = blockIdx.y / 3;
    int cb  = blockIdx.y % 3;
    const float* W  = sel == 0 ? wq : (sel == 1 ? wk : wv);
    const float* bi = sel == 0 ? bq : (sel == 1 ? bk : bv);
    float* Cout     = sel == 0 ? oq : (sel == 1 ? ok : ov);
    int act         = sel == 0 ? 1  : (sel == 1 ? 2  : 0);
    gemm_body(A, W, bi, Cout, CC, CC, act, 0, blockIdx.x, cb, As, Bs);
}

// ============================================================
// Kernel 4: linear attention v3 — reduced smem traffic + 2 blocks/SM.
// smem: ks,vs [N*48], kv[48*48], psum[2*48], ksum[48], zz[N]
//   row: 109.1 KB -> 2 blocks/SM; block = 256 threads.
// kv phase: threads 0..71, 4d x 8e tile, float4 k loads, full-N pass;
//           threads 96..191 compute ksum partials concurrently.
// out phase: 4n x 8e tiles, d-vectorized (q read from gmem/L2).
// ============================================================
__global__ __launch_bounds__(256) void attn_kernel(
        const float* __restrict__ q, const float* __restrict__ k,
        const float* __restrict__ v, float* __restrict__ o,
        int N, int isCol) {
    extern __shared__ float sm[];
    float* ks   = sm;                    // N*48
    float* vs   = ks + N * DH;           // N*48
    float* kv   = vs + N * DH;           // 48*48
    float* psum = kv + DH * DH;          // 2*48
    float* ksum = psum + 2 * DH;         // 48
    float* zz   = ksum + DH;             // N
    int g = blockIdx.x, h = blockIdx.y;
    int tid = threadIdx.x;

    // ---- stage k, v ----
    for (int lin = tid; lin < N * 12; lin += 256) {
        int n = lin / 12;
        int j = lin - n * 12;
        int t = isCol ? ((((g >> 8) * SS + n) << 8) + (g & 255)) : g * N + n;
        size_t base = (size_t)t * CC + h * DH + j * 4;
        ((float4*)ks)[lin] = *(const float4*)(k + base);
        ((float4*)vs)[lin] = *(const float4*)(v + base);
    }
    __syncthreads();

    // ---- kv (threads 0..71) and ksum partials (threads 96..191) ----
    if (tid < 72) {
        int dp = tid % 12;       // d block of 4
        int eo = tid / 12;       // e block of 8
        float acc[4][8];
        #pragma unroll
        for (int i = 0; i < 4; i++)
            #pragma unroll
            for (int j = 0; j < 8; j++) acc[i][j] = 0.f;
        for (int n = 0; n < N; n++) {
            float4 kk = ((const float4*)ks)[n * 12 + dp];
            float4 va = ((const float4*)vs)[n * 12 + eo * 2];
            float4 vb = ((const float4*)vs)[n * 12 + eo * 2 + 1];
            float kr[4] = {kk.x, kk.y, kk.z, kk.w};
            float vv[8] = {va.x, va.y, va.z, va.w, vb.x, vb.y, vb.z, vb.w};
            #pragma unroll
            for (int i = 0; i < 4; i++)
                #pragma unroll
                for (int j = 0; j < 8; j++) acc[i][j] += kr[i] * vv[j];
        }
        #pragma unroll
        for (int i = 0; i < 4; i++) {
            ((float4*)kv)[(dp * 4 + i) * 12 + eo * 2]     =
                make_float4(acc[i][0], acc[i][1], acc[i][2], acc[i][3]);
            ((float4*)kv)[(dp * 4 + i) * 12 + eo * 2 + 1] =
                make_float4(acc[i][4], acc[i][5], acc[i][6], acc[i][7]);
        }
    } else if (tid >= 96 && tid < 192) {
        int idx = tid - 96;
        int d  = idx % DH;
        int ch = idx / DH;
        int half = N >> 1;
        int n0 = ch * half;
        float s = 0.f;
        for (int n = n0; n < n0 + half; n++) s += ks[n * DH + d];
        psum[ch * DH + d] = s;
    }
    __syncthreads();

    if (tid < DH) ksum[tid] = psum[tid] + psum[DH + tid];
    __syncthreads();

    // ---- z[n] = 1/(q . ksum + eps) ----
    if (tid < N) {
        int n = tid;
        int t = isCol ? ((((g >> 8) * SS + n) << 8) + (g & 255)) : g * N + n;
        const float* qp = q + (size_t)t * CC + h * DH;
        float s = 0.f;
        #pragma unroll
        for (int j = 0; j < 12; j++) {
            float4 f = *(const float4*)(qp + j * 4);
            s += f.x * ksum[j*4] + f.y * ksum[j*4+1] + f.z * ksum[j*4+2] + f.w * ksum[j*4+3];
        }
        zz[n] = 1.0f / (s + 1e-6f);
    }
    __syncthreads();

    // ---- out: 4n x 8e tiles, d-vectorized ----
    int items = (N >> 2) * 6;
    for (int item = tid; item < items; item += 256) {
        int np = item / 6, eo = item % 6;
        int n0 = np * 4;
        const float* qp[4];
        int tt[4];
        #pragma unroll
        for (int i = 0; i < 4; i++) {
            int n = n0 + i;
            tt[i] = isCol ? ((((g >> 8) * SS + n) << 8) + (g & 255)) : g * N + n;
            qp[i] = q + (size_t)tt[i] * CC + h * DH;
        }
        float acc[4][8];
        #pragma unroll
        for (int i = 0; i < 4; i++)
            #pragma unroll
            for (int j = 0; j < 8; j++) acc[i][j] = 0.f;

        for (int j = 0; j < 12; j++) {
            float qr[4][4];
            #pragma unroll
            for (int i = 0; i < 4; i++) {
                float4 f = *(const float4*)(qp[i] + j * 4);
                qr[i][0] = f.x; qr[i][1] = f.y; qr[i][2] = f.z; qr[i][3] = f.w;
            }
            #pragma unroll
            for (int dd = 0; dd < 4; dd++) {
                int d = j * 4 + dd;
                float4 a = ((const float4*)kv)[d * 12 + eo * 2];
                float4 b = ((const float4*)kv)[d * 12 + eo * 2 + 1];
                #pragma unroll
                for (int i = 0; i < 4; i++) {
                    float qd = qr[i][dd];
                    acc[i][0] += qd * a.x; acc[i][1] += qd * a.y;
                    acc[i][2] += qd * a.z; acc[i][3] += qd * a.w;
                    acc[i][4] += qd * b.x; acc[i][5] += qd * b.y;
                    acc[i][6] += qd * b.z; acc[i][7] += qd * b.w;
                }
            }
        }
        #pragma unroll
        for (int i = 0; i < 4; i++) {
            float z = zz[n0 + i];
            float* op = o + (size_t)tt[i] * CC + h * DH + eo * 8;
            *(float4*)op       = make_float4(acc[i][0]*z, acc[i][1]*z, acc[i][2]*z, acc[i][3]*z);
            *(float4*)(op + 4) = make_float4(acc[i][4]*z, acc[i][5]*z, acc[i][6]*z, acc[i][7]*z);
        }
    }
}

// ============================================================
// Kernel 5: head
// ============================================================
__global__ void final_kernel(const float* __restrict__ x,
                             const float* __restrict__ pw,
                             const float* __restrict__ pb,
                             float* __restrict__ out) {
    int t = blockIdx.x * 8 + threadIdx.y;
    int lane = threadIdx.x;
    const float* xr = x + (size_t)t * CC;
    float s = 0.f;
    #pragma unroll
    for (int i = 0; i < 6; i++) {
        int c = lane + i * 32;
        s += xr[c] * pw[c];
    }
    #pragma unroll
    for (int o = 16; o; o >>= 1) s += __shfl_xor_sync(0xffffffffu, s, o);
    if (lane == 0) {
        float ov = s + pb[0];
        float sp = (ov > 20.f) ? ov : log1pf(expf(ov));
        out[t] = 1.0f / (1.0f + expf(-sp));
    }
}

// ============================================================
// Host orchestration
// ============================================================
extern "C" void kernel_launch(void* const* d_in, const int* in_sizes, int n_in,
                              void* d_out, int out_size) {
    const int*   tokens = (const int*)  d_in[0];
    const float* emb    = (const float*)d_in[1];
    const float* proj_w = (const float*)d_in[2];
    const float* proj_b = (const float*)d_in[3];
    const float* ln_g   = (const float*)d_in[4];
    const float* ln_b   = (const float*)d_in[5];
    const float* wq     = (const float*)d_in[6];
    const float* wk     = (const float*)d_in[7];
    const float* wv     = (const float*)d_in[8];
    const float* wo     = (const float*)d_in[9];
    const float* bq     = (const float*)d_in[10];
    const float* bk     = (const float*)d_in[11];
    const float* bv     = (const float*)d_in[12];
    const float* bo     = (const float*)d_in[13];
    const float* ffn_w1 = (const float*)d_in[14];
    const float* ffn_b1 = (const float*)d_in[15];
    const float* ffn_w2 = (const float*)d_in[16];
    const float* ffn_b2 = (const float*)d_in[17];
    const float* pw_w   = (const float*)d_in[18];
    const float* pw_b   = (const float*)d_in[19];
    float* out = (float*)d_out;

    float *px, *ph, *pq, *pk, *pv, *pf;
    cudaGetSymbolAddress((void**)&px, g_x);
    cudaGetSymbolAddress((void**)&ph, g_h);
    cudaGetSymbolAddress((void**)&pq, g_q);
    cudaGetSymbolAddress((void**)&pk, g_k);
    cudaGetSymbolAddress((void**)&pv, g_v);
    cudaGetSymbolAddress((void**)&pf, g_f1);

    // smem floats: 2*N*48 + 48*48 + 2*48 + 48 + N
    size_t smemRow = (size_t)(2 * LL * DH + DH * DH + 3 * DH + LL) * sizeof(float); // 109120
    size_t smemCol = (size_t)(2 * SS * DH + DH * DH + 3 * DH + SS) * sizeof(float); // 34624
    cudaFuncSetAttribute(attn_kernel, cudaFuncAttributeMaxDynamicSharedMemorySize, 112640);

    dim3 lnBlk(32, 8);
    dim3 gQKV(TT / BM, 9);
    dim3 g192(TT / BM, CC / BN);
    dim3 g768(TT / BM, C4 / BN);

    embed_kernel<<<TT, CC>>>(tokens, emb, proj_w, proj_b, px);

    for (int i = 0; i < NBLK; i++) {
        for (int dir = 0; dir < 2; dir++) {
            const float* lg = ln_g + (size_t)(i * 3 + dir) * CC;
            const float* lb = ln_b + (size_t)(i * 3 + dir) * CC;
            ln_kernel<<<TT / 8, lnBlk>>>(px, ph, lg, lb);

            size_t woff = ((size_t)i * 2 + dir) * CC * CC;
            size_t boff = ((size_t)i * 2 + dir) * CC;
            qkv_kernel<<<gQKV, 256>>>(ph, wq + woff, wk + woff, wv + woff,
                                      bq + boff, bk + boff, bv + boff, pq, pk, pv);

            if (dir == 0) {
                attn_kernel<<<dim3(BB * SS, HH), 256, smemRow>>>(pq, pk, pv, ph, LL, 0);
            } else {
                attn_kernel<<<dim3(BB * LL, HH), 256, smemCol>>>(pq, pk, pv, ph, SS, 1);
            }

            gemm_kernel<<<g192, 256>>>(ph, wo + woff, bo + boff, px, CC, CC, 0, 1);
        }
        const float* lg = ln_g + (size_t)(i * 3 + 2) * CC;
        const float* lb = ln_b + (size_t)(i * 3 + 2) * CC;
        ln_kernel<<<TT / 8, lnBlk>>>(px, ph, lg, lb);
        gemm_kernel<<<g768, 256>>>(ph, ffn_w1 + (size_t)i * C4 * CC, ffn_b1 + (size_t)i * C4,
                                   pf, CC, C4, 3, 0);
        gemm_kernel<<<g192, 256>>>(pf, ffn_w2 + (size_t)i * CC * C4, ffn_b2 + (size_t)i * CC,
                                   px, C4, CC, 0, 1);
    }

    final_kernel<<<TT / 8, lnBlk>>>(px, pw_w, pw_b, out);
}

// round 12
// speedup vs baseline: 1.5744x; 1.0705x over previous
#include <cuda_runtime.h>
#include <math.h>

// ---------------- problem constants ----------------
#define BB 2
#define SS 64
#define LL 256
#define CC 192
#define C4 768
#define HH 4
#define DH 48
#define TT (BB*SS*LL)      // 32768 tokens
#define NBLK 6

// ---------------- scratch ----------------
__device__ float g_x[TT*CC];
__device__ float g_h[TT*CC];
__device__ float g_q[TT*CC];
__device__ float g_k[TT*CC];
__device__ float g_v[TT*CC];
__device__ float g_f1[TT*C4];

__device__ __forceinline__ float elu1(float v) { return v > 0.0f ? v + 1.0f : expf(v); }
__device__ __forceinline__ float gelu_exact(float v) {
    return 0.5f * v * (1.0f + erff(v * 0.70710678118654752f));
}

// ============================================================
// Kernel 1: embed + proj + rotary
// ============================================================
__global__ void embed_kernel(const int* __restrict__ tokens,
                             const float* __restrict__ emb,
                             const float* __restrict__ pw,
                             const float* __restrict__ pb,
                             float* __restrict__ out) {
    int t = blockIdx.x;
    int c = threadIdx.x;
    __shared__ float e[64];
    __shared__ float xv[CC];
    __shared__ float invf[96];
    if (c < 64) e[c] = emb[tokens[t] * 64 + c];
    if (c >= 64 && c < 160) {
        int j = c - 64;
        invf[j] = powf(10000.0f, -(float)j / 96.0f);
    }
    __syncthreads();
    float s = pb[c];
    const float* wr = pw + c * 64;
    #pragma unroll
    for (int i = 0; i < 64; i++) s += e[i] * wr[i];
    xv[c] = s;
    __syncthreads();
    int l = t & (LL - 1);
    int c2 = (c < 96) ? c : c - 96;
    float a = (float)l * invf[c2];
    float cs = cosf(a), sn = sinf(a);
    float rot = (c < 96) ? -xv[c + 96] : xv[c - 96];
    out[(size_t)t * CC + c] = s * cs + rot * sn;
}

// ============================================================
// Kernel 2: LayerNorm over channels
// ============================================================
__global__ void ln_kernel(const float* __restrict__ x, float* __restrict__ h,
                          const float* __restrict__ g, const float* __restrict__ b) {
    int t = blockIdx.x * 8 + threadIdx.y;
    int lane = threadIdx.x;
    const float* xr = x + (size_t)t * CC;
    float v[6];
    float s = 0.f, ss = 0.f;
    #pragma unroll
    for (int i = 0; i < 6; i++) {
        v[i] = xr[lane + i * 32];
        s += v[i]; ss += v[i] * v[i];
    }
    #pragma unroll
    for (int o = 16; o; o >>= 1) {
        s  += __shfl_xor_sync(0xffffffffu, s, o);
        ss += __shfl_xor_sync(0xffffffffu, ss, o);
    }
    float m   = s * (1.0f / CC);
    float var = ss * (1.0f / CC) - m * m;
    float r   = rsqrtf(var + 1e-5f);
    float* hr = h + (size_t)t * CC;
    #pragma unroll
    for (int i = 0; i < 6; i++) {
        int c = lane + i * 32;
        hr[c] = (v[i] - m) * r * g[c] + b[c];
    }
}

// ============================================================
// TF32 tensor-core GEMM, fragment-major shared layout, ping-pong pipeline.
// Block tile 128x96, 8 warps (4x2), warp tile 32x48 (2x6 mma m16n8k8).
// ============================================================
#define BM 128
#define BN 96
#define BK 16
#define ASZ (BM*BK)
#define BSZ (BN*BK)

__device__ __forceinline__ void gemm_stage(
        float* As, float* Bs, const float4 aPre[2], const float4 bPre[2],
        int tid) {
    #pragma unroll
    for (int i = 0; i < 2; i++) {
        int lin = tid + i * 256;
        int m  = lin >> 2;
        int kq = (lin & 3) << 2;
        int mtile = m >> 4, r = m & 15;
        float fv[4] = {aPre[i].x, aPre[i].y, aPre[i].z, aPre[i].w};
        #pragma unroll
        for (int j = 0; j < 4; j++) {
            int k = kq + j;
            int ktile = k >> 3, kk = k & 7;
            int idx = (((mtile * 2 + ktile) * 32) + (r & 7) * 4 + (kk & 3)) * 4
                      + (r >> 3) + ((kk >> 2) << 1);
            As[idx] = fv[j];
        }
    }
    #pragma unroll
    for (int i = 0; i < 2; i++) {
        int lin = tid + i * 256;
        if (lin < BN * 4) {
            int n  = lin >> 2;
            int kq = (lin & 3) << 2;
            int ntile = n >> 3, c = n & 7;
            float fv[4] = {bPre[i].x, bPre[i].y, bPre[i].z, bPre[i].w};
            #pragma unroll
            for (int j = 0; j < 4; j++) {
                int k = kq + j;
                int ktile = k >> 3, kk = k & 7;
                int idx = (((ntile * 2 + ktile) * 32) + c * 4 + (kk & 3)) * 2 + (kk >> 2);
                Bs[idx] = fv[j];
            }
        }
    }
}

__device__ __forceinline__ void gemm_body(
        const float* __restrict__ A, const float* __restrict__ W,
        const float* __restrict__ bias, float* __restrict__ Cout,
        int K, int N, int act, int accFlag, int rowBlk, int colBlk,
        float* AsBuf, float* BsBuf) {
    int tid  = threadIdx.x;
    int lane = tid & 31;
    int warp = tid >> 5;
    int warpM = warp >> 1;
    int warpN = warp & 1;
    int gid = lane >> 2;
    int tig = lane & 3;
    int row0 = rowBlk * BM;
    int col0 = colBlk * BN;

    float acc[2][6][4];
    #pragma unroll
    for (int i = 0; i < 2; i++)
        #pragma unroll
        for (int j = 0; j < 6; j++)
            #pragma unroll
            for (int q = 0; q < 4; q++) acc[i][j][q] = 0.f;

    int aM0 = (tid) >> 2,       aK = (tid & 3) << 2;
    int aM1 = (tid + 256) >> 2;
    int bN0 = tid >> 2,         bK = (tid & 3) << 2;
    int bN1 = (tid + 256) >> 2;                      // valid when tid < 128
    const float* aPtr0 = A + (size_t)(row0 + aM0) * K + aK;
    const float* aPtr1 = A + (size_t)(row0 + aM1) * K + aK;
    const float* bPtr0 = W + (size_t)(col0 + bN0) * K + bK;
    const float* bPtr1 = W + (size_t)(col0 + (bN1 < BN ? bN1 : 0)) * K + bK;
    bool bHas1 = (tid < (BN * 4 - 256));

    float4 aPre[2]; float4 bPre[2];
    aPre[0] = *(const float4*)aPtr0;
    aPre[1] = *(const float4*)aPtr1;
    bPre[0] = *(const float4*)bPtr0;
    bPre[1] = bHas1 ? *(const float4*)bPtr1 : make_float4(0.f,0.f,0.f,0.f);

    int NT = K / BK;
    gemm_stage(AsBuf, BsBuf, aPre, bPre, tid);
    __syncthreads();

    for (int it = 0; it < NT; it++) {
        int cur = it & 1;
        if (it + 1 < NT) {
            int off = (it + 1) * BK;
            aPre[0] = *(const float4*)(aPtr0 + off);
            aPre[1] = *(const float4*)(aPtr1 + off);
            bPre[0] = *(const float4*)(bPtr0 + off);
            if (bHas1) bPre[1] = *(const float4*)(bPtr1 + off);
        }
        float* Ac = AsBuf + cur * ASZ;
        float* Bc = BsBuf + cur * BSZ;
        #pragma unroll
        for (int ktile = 0; ktile < 2; ktile++) {
            float4 af[2]; float2 bf[6];
            #pragma unroll
            for (int mt = 0; mt < 2; mt++) {
                int mtile = warpM * 2 + mt;
                af[mt] = ((const float4*)Ac)[(mtile * 2 + ktile) * 32 + lane];
            }
            #pragma unroll
            for (int nt = 0; nt < 6; nt++) {
                int ntile = warpN * 6 + nt;
                bf[nt] = ((const float2*)Bc)[(ntile * 2 + ktile) * 32 + lane];
            }
            #pragma unroll
            for (int mt = 0; mt < 2; mt++)
                #pragma unroll
                for (int nt = 0; nt < 6; nt++) {
                    asm volatile(
                        "mma.sync.aligned.m16n8k8.row.col.f32.tf32.tf32.f32 "
                        "{%0,%1,%2,%3}, {%4,%5,%6,%7}, {%8,%9}, {%0,%1,%2,%3};"
                        : "+f"(acc[mt][nt][0]), "+f"(acc[mt][nt][1]),
                          "+f"(acc[mt][nt][2]), "+f"(acc[mt][nt][3])
                        : "r"(__float_as_uint(af[mt].x)), "r"(__float_as_uint(af[mt].y)),
                          "r"(__float_as_uint(af[mt].z)), "r"(__float_as_uint(af[mt].w)),
                          "r"(__float_as_uint(bf[nt].x)), "r"(__float_as_uint(bf[nt].y)));
                }
        }
        if (it + 1 < NT) {
            gemm_stage(AsBuf + (cur ^ 1) * ASZ, BsBuf + (cur ^ 1) * BSZ, aPre, bPre, tid);
            __syncthreads();
        }
    }

    #pragma unroll
    for (int mt = 0; mt < 2; mt++) {
        int r0 = row0 + warpM * 32 + mt * 16 + gid;
        #pragma unroll
        for (int nt = 0; nt < 6; nt++) {
            int c0 = col0 + warpN * 48 + nt * 8 + tig * 2;
            #pragma unroll
            for (int half = 0; half < 2; half++) {
                int r = r0 + half * 8;
                #pragma unroll
                for (int q = 0; q < 2; q++) {
                    int c = c0 + q;
                    float v = acc[mt][nt][half * 2 + q] + bias[c];
                    if (act == 1)      v = elu1(v) * 0.14433756729740643f;
                    else if (act == 2) v = elu1(v);
                    else if (act == 3) v = gelu_exact(v);
                    size_t idx = (size_t)r * N + c;
                    if (accFlag) v += Cout[idx];
                    Cout[idx] = v;
                }
            }
        }
    }
}

__global__ __launch_bounds__(256) void gemm_kernel(
        const float* __restrict__ A, const float* __restrict__ W,
        const float* __restrict__ bias, float* __restrict__ Cout,
        int K, int N, int act, int accFlag) {
    __shared__ float As[2 * ASZ];
    __shared__ float Bs[2 * BSZ];
    gemm_body(A, W, bias, Cout, K, N, act, accFlag, blockIdx.x, blockIdx.y, As, Bs);
}

// fused Q/K/V: blockIdx.y in [0,6): sel = y>>1 chooses {q,k,v}, colBlk = y&1
__global__ __launch_bounds__(256) void qkv_kernel(
        const float* __restrict__ A,
        const float* __restrict__ wq, const float* __restrict__ wk, const float* __restrict__ wv,
        const float* __restrict__ bq, const float* __restrict__ bk, const float* __restrict__ bv,
        float* __restrict__ oq, float* __restrict__ ok, float* __restrict__ ov) {
    __shared__ float As[2 * ASZ];
    __shared__ float Bs[2 * BSZ];
    int sel = blockIdx.y >> 1;
    int cb  = blockIdx.y & 1;
    const float* W  = sel == 0 ? wq : (sel == 1 ? wk : wv);
    const float* bi = sel == 0 ? bq : (sel == 1 ? bk : bv);
    float* Cout     = sel == 0 ? oq : (sel == 1 ? ok : ov);
    int act         = sel == 0 ? 1  : (sel == 1 ? 2  : 0);
    gemm_body(A, W, bi, Cout, CC, CC, act, 0, blockIdx.x, cb, As, Bs);
}

// ============================================================
// Kernel 4: linear attention (unchanged from R11 win)
// ============================================================
__global__ __launch_bounds__(256) void attn_kernel(
        const float* __restrict__ q, const float* __restrict__ k,
        const float* __restrict__ v, float* __restrict__ o,
        int N, int isCol) {
    extern __shared__ float sm[];
    float* ks   = sm;                    // N*48
    float* vs   = ks + N * DH;           // N*48
    float* kv   = vs + N * DH;           // 48*48
    float* psum = kv + DH * DH;          // 2*48
    float* ksum = psum + 2 * DH;         // 48
    float* zz   = ksum + DH;             // N
    int g = blockIdx.x, h = blockIdx.y;
    int tid = threadIdx.x;

    for (int lin = tid; lin < N * 12; lin += 256) {
        int n = lin / 12;
        int j = lin - n * 12;
        int t = isCol ? ((((g >> 8) * SS + n) << 8) + (g & 255)) : g * N + n;
        size_t base = (size_t)t * CC + h * DH + j * 4;
        ((float4*)ks)[lin] = *(const float4*)(k + base);
        ((float4*)vs)[lin] = *(const float4*)(v + base);
    }
    __syncthreads();

    if (tid < 72) {
        int dp = tid % 12;
        int eo = tid / 12;
        float acc[4][8];
        #pragma unroll
        for (int i = 0; i < 4; i++)
            #pragma unroll
            for (int j = 0; j < 8; j++) acc[i][j] = 0.f;
        for (int n = 0; n < N; n++) {
            float4 kk = ((const float4*)ks)[n * 12 + dp];
            float4 va = ((const float4*)vs)[n * 12 + eo * 2];
            float4 vb = ((const float4*)vs)[n * 12 + eo * 2 + 1];
            float kr[4] = {kk.x, kk.y, kk.z, kk.w};
            float vv[8] = {va.x, va.y, va.z, va.w, vb.x, vb.y, vb.z, vb.w};
            #pragma unroll
            for (int i = 0; i < 4; i++)
                #pragma unroll
                for (int j = 0; j < 8; j++) acc[i][j] += kr[i] * vv[j];
        }
        #pragma unroll
        for (int i = 0; i < 4; i++) {
            ((float4*)kv)[(dp * 4 + i) * 12 + eo * 2]     =
                make_float4(acc[i][0], acc[i][1], acc[i][2], acc[i][3]);
            ((float4*)kv)[(dp * 4 + i) * 12 + eo * 2 + 1] =
                make_float4(acc[i][4], acc[i][5], acc[i][6], acc[i][7]);
        }
    } else if (tid >= 96 && tid < 192) {
        int idx = tid - 96;
        int d  = idx % DH;
        int ch = idx / DH;
        int half = N >> 1;
        int n0 = ch * half;
        float s = 0.f;
        for (int n = n0; n < n0 + half; n++) s += ks[n * DH + d];
        psum[ch * DH + d] = s;
    }
    __syncthreads();

    if (tid < DH) ksum[tid] = psum[tid] + psum[DH + tid];
    __syncthreads();

    if (tid < N) {
        int n = tid;
        int t = isCol ? ((((g >> 8) * SS + n) << 8) + (g & 255)) : g * N + n;
        const float* qp = q + (size_t)t * CC + h * DH;
        float s = 0.f;
        #pragma unroll
        for (int j = 0; j < 12; j++) {
            float4 f = *(const float4*)(qp + j * 4);
            s += f.x * ksum[j*4] + f.y * ksum[j*4+1] + f.z * ksum[j*4+2] + f.w * ksum[j*4+3];
        }
        zz[n] = 1.0f / (s + 1e-6f);
    }
    __syncthreads();

    int items = (N >> 2) * 6;
    for (int item = tid; item < items; item += 256) {
        int np = item / 6, eo = item % 6;
        int n0 = np * 4;
        const float* qp[4];
        int tt[4];
        #pragma unroll
        for (int i = 0; i < 4; i++) {
            int n = n0 + i;
            tt[i] = isCol ? ((((g >> 8) * SS + n) << 8) + (g & 255)) : g * N + n;
            qp[i] = q + (size_t)tt[i] * CC + h * DH;
        }
        float acc[4][8];
        #pragma unroll
        for (int i = 0; i < 4; i++)
            #pragma unroll
            for (int j = 0; j < 8; j++) acc[i][j] = 0.f;

        for (int j = 0; j < 12; j++) {
            float qr[4][4];
            #pragma unroll
            for (int i = 0; i < 4; i++) {
                float4 f = *(const float4*)(qp[i] + j * 4);
                qr[i][0] = f.x; qr[i][1] = f.y; qr[i][2] = f.z; qr[i][3] = f.w;
            }
            #pragma unroll
            for (int dd = 0; dd < 4; dd++) {
                int d = j * 4 + dd;
                float4 a = ((const float4*)kv)[d * 12 + eo * 2];
                float4 b = ((const float4*)kv)[d * 12 + eo * 2 + 1];
                #pragma unroll
                for (int i = 0; i < 4; i++) {
                    float qd = qr[i][dd];
                    acc[i][0] += qd * a.x; acc[i][1] += qd * a.y;
                    acc[i][2] += qd * a.z; acc[i][3] += qd * a.w;
                    acc[i][4] += qd * b.x; acc[i][5] += qd * b.y;
                    acc[i][6] += qd * b.z; acc[i][7] += qd * b.w;
                }
            }
        }
        #pragma unroll
        for (int i = 0; i < 4; i++) {
            float z = zz[n0 + i];
            float* op = o + (size_t)tt[i] * CC + h * DH + eo * 8;
            *(float4*)op       = make_float4(acc[i][0]*z, acc[i][1]*z, acc[i][2]*z, acc[i][3]*z);
            *(float4*)(op + 4) = make_float4(acc[i][4]*z, acc[i][5]*z, acc[i][6]*z, acc[i][7]*z);
        }
    }
}

// ============================================================
// Kernel 5: head
// ============================================================
__global__ void final_kernel(const float* __restrict__ x,
                             const float* __restrict__ pw,
                             const float* __restrict__ pb,
                             float* __restrict__ out) {
    int t = blockIdx.x * 8 + threadIdx.y;
    int lane = threadIdx.x;
    const float* xr = x + (size_t)t * CC;
    float s = 0.f;
    #pragma unroll
    for (int i = 0; i < 6; i++) {
        int c = lane + i * 32;
        s += xr[c] * pw[c];
    }
    #pragma unroll
    for (int o = 16; o; o >>= 1) s += __shfl_xor_sync(0xffffffffu, s, o);
    if (lane == 0) {
        float ov = s + pb[0];
        float sp = (ov > 20.f) ? ov : log1pf(expf(ov));
        out[t] = 1.0f / (1.0f + expf(-sp));
    }
}

// ============================================================
// Host orchestration
// ============================================================
extern "C" void kernel_launch(void* const* d_in, const int* in_sizes, int n_in,
                              void* d_out, int out_size) {
    const int*   tokens = (const int*)  d_in[0];
    const float* emb    = (const float*)d_in[1];
    const float* proj_w = (const float*)d_in[2];
    const float* proj_b = (const float*)d_in[3];
    const float* ln_g   = (const float*)d_in[4];
    const float* ln_b   = (const float*)d_in[5];
    const float* wq     = (const float*)d_in[6];
    const float* wk     = (const float*)d_in[7];
    const float* wv     = (const float*)d_in[8];
    const float* wo     = (const float*)d_in[9];
    const float* bq     = (const float*)d_in[10];
    const float* bk     = (const float*)d_in[11];
    const float* bv     = (const float*)d_in[12];
    const float* bo     = (const float*)d_in[13];
    const float* ffn_w1 = (const float*)d_in[14];
    const float* ffn_b1 = (const float*)d_in[15];
    const float* ffn_w2 = (const float*)d_in[16];
    const float* ffn_b2 = (const float*)d_in[17];
    const float* pw_w   = (const float*)d_in[18];
    const float* pw_b   = (const float*)d_in[19];
    float* out = (float*)d_out;

    float *px, *ph, *pq, *pk, *pv, *pf;
    cudaGetSymbolAddress((void**)&px, g_x);
    cudaGetSymbolAddress((void**)&ph, g_h);
    cudaGetSymbolAddress((void**)&pq, g_q);
    cudaGetSymbolAddress((void**)&pk, g_k);
    cudaGetSymbolAddress((void**)&pv, g_v);
    cudaGetSymbolAddress((void**)&pf, g_f1);

    size_t smemRow = (size_t)(2 * LL * DH + DH * DH + 3 * DH + LL) * sizeof(float); // 109120
    size_t smemCol = (size_t)(2 * SS * DH + DH * DH + 3 * DH + SS) * sizeof(float); // 34624
    cudaFuncSetAttribute(attn_kernel, cudaFuncAttributeMaxDynamicSharedMemorySize, 112640);

    dim3 lnBlk(32, 8);
    dim3 gQKV(TT / BM, 6);          // 3 weights x 2 col-blocks of 96
    dim3 g192(TT / BM, CC / BN);    // (256, 2)
    dim3 g768(TT / BM, C4 / BN);    // (256, 8)

    embed_kernel<<<TT, CC>>>(tokens, emb, proj_w, proj_b, px);

    for (int i = 0; i < NBLK; i++) {
        for (int dir = 0; dir < 2; dir++) {
            const float* lg = ln_g + (size_t)(i * 3 + dir) * CC;
            const float* lb = ln_b + (size_t)(i * 3 + dir) * CC;
            ln_kernel<<<TT / 8, lnBlk>>>(px, ph, lg, lb);

            size_t woff = ((size_t)i * 2 + dir) * CC * CC;
            size_t boff = ((size_t)i * 2 + dir) * CC;
            qkv_kernel<<<gQKV, 256>>>(ph, wq + woff, wk + woff, wv + woff,
                                      bq + boff, bk + boff, bv + boff, pq, pk, pv);

            if (dir == 0) {
                attn_kernel<<<dim3(BB * SS, HH), 256, smemRow>>>(pq, pk, pv, ph, LL, 0);
            } else {
                attn_kernel<<<dim3(BB * LL, HH), 256, smemCol>>>(pq, pk, pv, ph, SS, 1);
            }

            gemm_kernel<<<g192, 256>>>(ph, wo + woff, bo + boff, px, CC, CC, 0, 1);
        }
        const float* lg = ln_g + (size_t)(i * 3 + 2) * CC;
        const float* lb = ln_b + (size_t)(i * 3 + 2) * CC;
        ln_kernel<<<TT / 8, lnBlk>>>(px, ph, lg, lb);
        gemm_kernel<<<g768, 256>>>(ph, ffn_w1 + (size_t)i * C4 * CC, ffn_b1 + (size_t)i * C4,
                                   pf, CC, C4, 3, 0);
        gemm_kernel<<<g192, 256>>>(pf, ffn_w2 + (size_t)i * CC * C4, ffn_b2 + (size_t)i * CC,
                                   px, C4, CC, 0, 1);
    }

    final_kernel<<<TT / 8, lnBlk>>>(px, pw_w, pw_b, out);
}

// round 13
// speedup vs baseline: 1.5751x; 1.0005x over previous
#include <cuda_runtime.h>
#include <math.h>

// ---------------- problem constants ----------------
#define BB 2
#define SS 64
#define LL 256
#define CC 192
#define C4 768
#define HH 4
#define DH 48
#define TT (BB*SS*LL)      // 32768 tokens
#define NBLK 6

// ---------------- scratch ----------------
__device__ float g_x[TT*CC];
__device__ float g_h[TT*CC];
__device__ float g_q[TT*CC];
__device__ float g_k[TT*CC];
__device__ float g_v[TT*CC];
__device__ float g_f1[TT*C4];
__device__ float2 g_stats[TT];   // per-token (mean, rstd)

__device__ __forceinline__ float elu1(float v) { return v > 0.0f ? v + 1.0f : expf(v); }
__device__ __forceinline__ float gelu_exact(float v) {
    return 0.5f * v * (1.0f + erff(v * 0.70710678118654752f));
}

// ============================================================
// Kernel 1: embed + proj + rotary
// ============================================================
__global__ void embed_kernel(const int* __restrict__ tokens,
                             const float* __restrict__ emb,
                             const float* __restrict__ pw,
                             const float* __restrict__ pb,
                             float* __restrict__ out) {
    int t = blockIdx.x;
    int c = threadIdx.x;
    __shared__ float e[64];
    __shared__ float xv[CC];
    __shared__ float invf[96];
    if (c < 64) e[c] = emb[tokens[t] * 64 + c];
    if (c >= 64 && c < 160) {
        int j = c - 64;
        invf[j] = powf(10000.0f, -(float)j / 96.0f);
    }
    __syncthreads();
    float s = pb[c];
    const float* wr = pw + c * 64;
    #pragma unroll
    for (int i = 0; i < 64; i++) s += e[i] * wr[i];
    xv[c] = s;
    __syncthreads();
    int l = t & (LL - 1);
    int c2 = (c < 96) ? c : c - 96;
    float a = (float)l * invf[c2];
    float cs = cosf(a), sn = sinf(a);
    float rot = (c < 96) ? -xv[c + 96] : xv[c - 96];
    out[(size_t)t * CC + c] = s * cs + rot * sn;
}

// ============================================================
// Kernel 2: LN stats only — (mean, rstd) per token
// ============================================================
__global__ void ln_stats_kernel(const float* __restrict__ x,
                                float2* __restrict__ stats) {
    int t = blockIdx.x * 8 + threadIdx.y;
    int lane = threadIdx.x;
    const float* xr = x + (size_t)t * CC;
    float s = 0.f, ss = 0.f;
    #pragma unroll
    for (int i = 0; i < 6; i++) {
        float v = xr[lane + i * 32];
        s += v; ss += v * v;
    }
    #pragma unroll
    for (int o = 16; o; o >>= 1) {
        s  += __shfl_xor_sync(0xffffffffu, s, o);
        ss += __shfl_xor_sync(0xffffffffu, ss, o);
    }
    if (lane == 0) {
        float m   = s * (1.0f / CC);
        float var = ss * (1.0f / CC) - m * m;
        stats[t] = make_float2(m, rsqrtf(var + 1e-5f));
    }
}

// ============================================================
// TF32 tensor-core GEMM, fragment-major shared layout, ping-pong pipeline.
// Block tile 128x96, 8 warps (4x2), warp tile 32x48 (2x6 mma m16n8k8).
// Template LN: apply (x-m)*r*g[k]+b[k] to A during prefetch.
// ============================================================
#define BM 128
#define BN 96
#define BK 16
#define ASZ (BM*BK)
#define BSZ (BN*BK)

__device__ __forceinline__ void gemm_stage(
        float* As, float* Bs, const float4 aPre[2], const float4 bPre[2],
        int tid) {
    #pragma unroll
    for (int i = 0; i < 2; i++) {
        int lin = tid + i * 256;
        int m  = lin >> 2;
        int kq = (lin & 3) << 2;
        int mtile = m >> 4, r = m & 15;
        float fv[4] = {aPre[i].x, aPre[i].y, aPre[i].z, aPre[i].w};
        #pragma unroll
        for (int j = 0; j < 4; j++) {
            int k = kq + j;
            int ktile = k >> 3, kk = k & 7;
            int idx = (((mtile * 2 + ktile) * 32) + (r & 7) * 4 + (kk & 3)) * 4
                      + (r >> 3) + ((kk >> 2) << 1);
            As[idx] = fv[j];
        }
    }
    #pragma unroll
    for (int i = 0; i < 2; i++) {
        int lin = tid + i * 256;
        if (lin < BN * 4) {
            int n  = lin >> 2;
            int kq = (lin & 3) << 2;
            int ntile = n >> 3, c = n & 7;
            float fv[4] = {bPre[i].x, bPre[i].y, bPre[i].z, bPre[i].w};
            #pragma unroll
            for (int j = 0; j < 4; j++) {
                int k = kq + j;
                int ktile = k >> 3, kk = k & 7;
                int idx = (((ntile * 2 + ktile) * 32) + c * 4 + (kk & 3)) * 2 + (kk >> 2);
                Bs[idx] = fv[j];
            }
        }
    }
}

template<bool LN>
__device__ __forceinline__ void gemm_body(
        const float* __restrict__ A, const float* __restrict__ W,
        const float* __restrict__ bias, float* __restrict__ Cout,
        int K, int N, int act, int accFlag, int rowBlk, int colBlk,
        float* AsBuf, float* BsBuf,
        const float2* __restrict__ stats,
        const float* __restrict__ lnG, const float* __restrict__ lnB) {
    int tid  = threadIdx.x;
    int lane = tid & 31;
    int warp = tid >> 5;
    int warpM = warp >> 1;
    int warpN = warp & 1;
    int gid = lane >> 2;
    int tig = lane & 3;
    int row0 = rowBlk * BM;
    int col0 = colBlk * BN;

    float acc[2][6][4];
    #pragma unroll
    for (int i = 0; i < 2; i++)
        #pragma unroll
        for (int j = 0; j < 6; j++)
            #pragma unroll
            for (int q = 0; q < 4; q++) acc[i][j][q] = 0.f;

    int aM0 = (tid) >> 2,       aK = (tid & 3) << 2;
    int aM1 = (tid + 256) >> 2;
    int bN0 = tid >> 2,         bK = (tid & 3) << 2;
    int bN1 = (tid + 256) >> 2;
    const float* aPtr0 = A + (size_t)(row0 + aM0) * K + aK;
    const float* aPtr1 = A + (size_t)(row0 + aM1) * K + aK;
    const float* bPtr0 = W + (size_t)(col0 + bN0) * K + bK;
    const float* bPtr1 = W + (size_t)(col0 + (bN1 < BN ? bN1 : 0)) * K + bK;
    bool bHas1 = (tid < (BN * 4 - 256));

    float2 st0, st1;
    if (LN) {
        st0 = stats[row0 + aM0];
        st1 = stats[row0 + aM1];
    }

    float4 aPre[2]; float4 bPre[2];
    aPre[0] = *(const float4*)aPtr0;
    aPre[1] = *(const float4*)aPtr1;
    bPre[0] = *(const float4*)bPtr0;
    bPre[1] = bHas1 ? *(const float4*)bPtr1 : make_float4(0.f,0.f,0.f,0.f);
    if (LN) {
        float4 g4 = *(const float4*)(lnG + aK);
        float4 b4 = *(const float4*)(lnB + aK);
        aPre[0].x = (aPre[0].x - st0.x) * st0.y * g4.x + b4.x;
        aPre[0].y = (aPre[0].y - st0.x) * st0.y * g4.y + b4.y;
        aPre[0].z = (aPre[0].z - st0.x) * st0.y * g4.z + b4.z;
        aPre[0].w = (aPre[0].w - st0.x) * st0.y * g4.w + b4.w;
        aPre[1].x = (aPre[1].x - st1.x) * st1.y * g4.x + b4.x;
        aPre[1].y = (aPre[1].y - st1.x) * st1.y * g4.y + b4.y;
        aPre[1].z = (aPre[1].z - st1.x) * st1.y * g4.z + b4.z;
        aPre[1].w = (aPre[1].w - st1.x) * st1.y * g4.w + b4.w;
    }

    int NT = K / BK;
    gemm_stage(AsBuf, BsBuf, aPre, bPre, tid);
    __syncthreads();

    for (int it = 0; it < NT; it++) {
        int cur = it & 1;
        if (it + 1 < NT) {
            int off = (it + 1) * BK;
            aPre[0] = *(const float4*)(aPtr0 + off);
            aPre[1] = *(const float4*)(aPtr1 + off);
            bPre[0] = *(const float4*)(bPtr0 + off);
            if (bHas1) bPre[1] = *(const float4*)(bPtr1 + off);
            if (LN) {
                int kb = off + aK;
                float4 g4 = *(const float4*)(lnG + kb);
                float4 b4 = *(const float4*)(lnB + kb);
                aPre[0].x = (aPre[0].x - st0.x) * st0.y * g4.x + b4.x;
                aPre[0].y = (aPre[0].y - st0.x) * st0.y * g4.y + b4.y;
                aPre[0].z = (aPre[0].z - st0.x) * st0.y * g4.z + b4.z;
                aPre[0].w = (aPre[0].w - st0.x) * st0.y * g4.w + b4.w;
                aPre[1].x = (aPre[1].x - st1.x) * st1.y * g4.x + b4.x;
                aPre[1].y = (aPre[1].y - st1.x) * st1.y * g4.y + b4.y;
                aPre[1].z = (aPre[1].z - st1.x) * st1.y * g4.z + b4.z;
                aPre[1].w = (aPre[1].w - st1.x) * st1.y * g4.w + b4.w;
            }
        }
        float* Ac = AsBuf + cur * ASZ;
        float* Bc = BsBuf + cur * BSZ;
        #pragma unroll
        for (int ktile = 0; ktile < 2; ktile++) {
            float4 af[2]; float2 bf[6];
            #pragma unroll
            for (int mt = 0; mt < 2; mt++) {
                int mtile = warpM * 2 + mt;
                af[mt] = ((const float4*)Ac)[(mtile * 2 + ktile) * 32 + lane];
            }
            #pragma unroll
            for (int nt = 0; nt < 6; nt++) {
                int ntile = warpN * 6 + nt;
                bf[nt] = ((const float2*)Bc)[(ntile * 2 + ktile) * 32 + lane];
            }
            #pragma unroll
            for (int mt = 0; mt < 2; mt++)
                #pragma unroll
                for (int nt = 0; nt < 6; nt++) {
                    asm volatile(
                        "mma.sync.aligned.m16n8k8.row.col.f32.tf32.tf32.f32 "
                        "{%0,%1,%2,%3}, {%4,%5,%6,%7}, {%8,%9}, {%0,%1,%2,%3};"
                        : "+f"(acc[mt][nt][0]), "+f"(acc[mt][nt][1]),
                          "+f"(acc[mt][nt][2]), "+f"(acc[mt][nt][3])
                        : "r"(__float_as_uint(af[mt].x)), "r"(__float_as_uint(af[mt].y)),
                          "r"(__float_as_uint(af[mt].z)), "r"(__float_as_uint(af[mt].w)),
                          "r"(__float_as_uint(bf[nt].x)), "r"(__float_as_uint(bf[nt].y)));
                }
        }
        if (it + 1 < NT) {
            gemm_stage(AsBuf + (cur ^ 1) * ASZ, BsBuf + (cur ^ 1) * BSZ, aPre, bPre, tid);
            __syncthreads();
        }
    }

    #pragma unroll
    for (int mt = 0; mt < 2; mt++) {
        int r0 = row0 + warpM * 32 + mt * 16 + gid;
        #pragma unroll
        for (int nt = 0; nt < 6; nt++) {
            int c0 = col0 + warpN * 48 + nt * 8 + tig * 2;
            #pragma unroll
            for (int half = 0; half < 2; half++) {
                int r = r0 + half * 8;
                #pragma unroll
                for (int q = 0; q < 2; q++) {
                    int c = c0 + q;
                    float v = acc[mt][nt][half * 2 + q] + bias[c];
                    if (act == 1)      v = elu1(v) * 0.14433756729740643f;
                    else if (act == 2) v = elu1(v);
                    else if (act == 3) v = gelu_exact(v);
                    size_t idx = (size_t)r * N + c;
                    if (accFlag) v += Cout[idx];
                    Cout[idx] = v;
                }
            }
        }
    }
}

__global__ __launch_bounds__(256) void gemm_kernel(
        const float* __restrict__ A, const float* __restrict__ W,
        const float* __restrict__ bias, float* __restrict__ Cout,
        int K, int N, int act, int accFlag) {
    __shared__ float As[2 * ASZ];
    __shared__ float Bs[2 * BSZ];
    gemm_body<false>(A, W, bias, Cout, K, N, act, accFlag, blockIdx.x, blockIdx.y,
                     As, Bs, nullptr, nullptr, nullptr);
}

// LN-fused GEMM (for FFN1): A = LN(x) applied on the fly
__global__ __launch_bounds__(256) void gemm_ln_kernel(
        const float* __restrict__ A, const float* __restrict__ W,
        const float* __restrict__ bias, float* __restrict__ Cout,
        int K, int N, int act, int accFlag,
        const float2* __restrict__ stats,
        const float* __restrict__ lnG, const float* __restrict__ lnB) {
    __shared__ float As[2 * ASZ];
    __shared__ float Bs[2 * BSZ];
    gemm_body<true>(A, W, bias, Cout, K, N, act, accFlag, blockIdx.x, blockIdx.y,
                    As, Bs, stats, lnG, lnB);
}

// fused Q/K/V with LN: blockIdx.y in [0,6): sel = y>>1, colBlk = y&1
__global__ __launch_bounds__(256) void qkv_kernel(
        const float* __restrict__ A,
        const float* __restrict__ wq, const float* __restrict__ wk, const float* __restrict__ wv,
        const float* __restrict__ bq, const float* __restrict__ bk, const float* __restrict__ bv,
        float* __restrict__ oq, float* __restrict__ ok, float* __restrict__ ov,
        const float2* __restrict__ stats,
        const float* __restrict__ lnG, const float* __restrict__ lnB) {
    __shared__ float As[2 * ASZ];
    __shared__ float Bs[2 * BSZ];
    int sel = blockIdx.y >> 1;
    int cb  = blockIdx.y & 1;
    const float* W  = sel == 0 ? wq : (sel == 1 ? wk : wv);
    const float* bi = sel == 0 ? bq : (sel == 1 ? bk : bv);
    float* Cout     = sel == 0 ? oq : (sel == 1 ? ok : ov);
    int act         = sel == 0 ? 1  : (sel == 1 ? 2  : 0);
    gemm_body<true>(A, W, bi, Cout, CC, CC, act, 0, blockIdx.x, cb,
                    As, Bs, stats, lnG, lnB);
}

// ============================================================
// Kernel 4: linear attention (unchanged from R11/R12 win)
// ============================================================
__global__ __launch_bounds__(256) void attn_kernel(
        const float* __restrict__ q, const float* __restrict__ k,
        const float* __restrict__ v, float* __restrict__ o,
        int N, int isCol) {
    extern __shared__ float sm[];
    float* ks   = sm;
    float* vs   = ks + N * DH;
    float* kv   = vs + N * DH;
    float* psum = kv + DH * DH;
    float* ksum = psum + 2 * DH;
    float* zz   = ksum + DH;
    int g = blockIdx.x, h = blockIdx.y;
    int tid = threadIdx.x;

    for (int lin = tid; lin < N * 12; lin += 256) {
        int n = lin / 12;
        int j = lin - n * 12;
        int t = isCol ? ((((g >> 8) * SS + n) << 8) + (g & 255)) : g * N + n;
        size_t base = (size_t)t * CC + h * DH + j * 4;
        ((float4*)ks)[lin] = *(const float4*)(k + base);
        ((float4*)vs)[lin] = *(const float4*)(v + base);
    }
    __syncthreads();

    if (tid < 72) {
        int dp = tid % 12;
        int eo = tid / 12;
        float acc[4][8];
        #pragma unroll
        for (int i = 0; i < 4; i++)
            #pragma unroll
            for (int j = 0; j < 8; j++) acc[i][j] = 0.f;
        for (int n = 0; n < N; n++) {
            float4 kk = ((const float4*)ks)[n * 12 + dp];
            float4 va = ((const float4*)vs)[n * 12 + eo * 2];
            float4 vb = ((const float4*)vs)[n * 12 + eo * 2 + 1];
            float kr[4] = {kk.x, kk.y, kk.z, kk.w};
            float vv[8] = {va.x, va.y, va.z, va.w, vb.x, vb.y, vb.z, vb.w};
            #pragma unroll
            for (int i = 0; i < 4; i++)
                #pragma unroll
                for (int j = 0; j < 8; j++) acc[i][j] += kr[i] * vv[j];
        }
        #pragma unroll
        for (int i = 0; i < 4; i++) {
            ((float4*)kv)[(dp * 4 + i) * 12 + eo * 2]     =
                make_float4(acc[i][0], acc[i][1], acc[i][2], acc[i][3]);
            ((float4*)kv)[(dp * 4 + i) * 12 + eo * 2 + 1] =
                make_float4(acc[i][4], acc[i][5], acc[i][6], acc[i][7]);
        }
    } else if (tid >= 96 && tid < 192) {
        int idx = tid - 96;
        int d  = idx % DH;
        int ch = idx / DH;
        int half = N >> 1;
        int n0 = ch * half;
        float s = 0.f;
        for (int n = n0; n < n0 + half; n++) s += ks[n * DH + d];
        psum[ch * DH + d] = s;
    }
    __syncthreads();

    if (tid < DH) ksum[tid] = psum[tid] + psum[DH + tid];
    __syncthreads();

    if (tid < N) {
        int n = tid;
        int t = isCol ? ((((g >> 8) * SS + n) << 8) + (g & 255)) : g * N + n;
        const float* qp = q + (size_t)t * CC + h * DH;
        float s = 0.f;
        #pragma unroll
        for (int j = 0; j < 12; j++) {
            float4 f = *(const float4*)(qp + j * 4);
            s += f.x * ksum[j*4] + f.y * ksum[j*4+1] + f.z * ksum[j*4+2] + f.w * ksum[j*4+3];
        }
        zz[n] = 1.0f / (s + 1e-6f);
    }
    __syncthreads();

    int items = (N >> 2) * 6;
    for (int item = tid; item < items; item += 256) {
        int np = item / 6, eo = item % 6;
        int n0 = np * 4;
        const float* qp[4];
        int tt[4];
        #pragma unroll
        for (int i = 0; i < 4; i++) {
            int n = n0 + i;
            tt[i] = isCol ? ((((g >> 8) * SS + n) << 8) + (g & 255)) : g * N + n;
            qp[i] = q + (size_t)tt[i] * CC + h * DH;
        }
        float acc[4][8];
        #pragma unroll
        for (int i = 0; i < 4; i++)
            #pragma unroll
            for (int j = 0; j < 8; j++) acc[i][j] = 0.f;

        for (int j = 0; j < 12; j++) {
            float qr[4][4];
            #pragma unroll
            for (int i = 0; i < 4; i++) {
                float4 f = *(const float4*)(qp[i] + j * 4);
                qr[i][0] = f.x; qr[i][1] = f.y; qr[i][2] = f.z; qr[i][3] = f.w;
            }
            #pragma unroll
            for (int dd = 0; dd < 4; dd++) {
                int d = j * 4 + dd;
                float4 a = ((const float4*)kv)[d * 12 + eo * 2];
                float4 b = ((const float4*)kv)[d * 12 + eo * 2 + 1];
                #pragma unroll
                for (int i = 0; i < 4; i++) {
                    float qd = qr[i][dd];
                    acc[i][0] += qd * a.x; acc[i][1] += qd * a.y;
                    acc[i][2] += qd * a.z; acc[i][3] += qd * a.w;
                    acc[i][4] += qd * b.x; acc[i][5] += qd * b.y;
                    acc[i][6] += qd * b.z; acc[i][7] += qd * b.w;
                }
            }
        }
        #pragma unroll
        for (int i = 0; i < 4; i++) {
            float z = zz[n0 + i];
            float* op = o + (size_t)tt[i] * CC + h * DH + eo * 8;
            *(float4*)op       = make_float4(acc[i][0]*z, acc[i][1]*z, acc[i][2]*z, acc[i][3]*z);
            *(float4*)(op + 4) = make_float4(acc[i][4]*z, acc[i][5]*z, acc[i][6]*z, acc[i][7]*z);
        }
    }
}

// ============================================================
// Kernel 5: head
// ============================================================
__global__ void final_kernel(const float* __restrict__ x,
                             const float* __restrict__ pw,
                             const float* __restrict__ pb,
                             float* __restrict__ out) {
    int t = blockIdx.x * 8 + threadIdx.y;
    int lane = threadIdx.x;
    const float* xr = x + (size_t)t * CC;
    float s = 0.f;
    #pragma unroll
    for (int i = 0; i < 6; i++) {
        int c = lane + i * 32;
        s += xr[c] * pw[c];
    }
    #pragma unroll
    for (int o = 16; o; o >>= 1) s += __shfl_xor_sync(0xffffffffu, s, o);
    if (lane == 0) {
        float ov = s + pb[0];
        float sp = (ov > 20.f) ? ov : log1pf(expf(ov));
        out[t] = 1.0f / (1.0f + expf(-sp));
    }
}

// ============================================================
// Host orchestration
// ============================================================
extern "C" void kernel_launch(void* const* d_in, const int* in_sizes, int n_in,
                              void* d_out, int out_size) {
    const int*   tokens = (const int*)  d_in[0];
    const float* emb    = (const float*)d_in[1];
    const float* proj_w = (const float*)d_in[2];
    const float* proj_b = (const float*)d_in[3];
    const float* ln_g   = (const float*)d_in[4];
    const float* ln_b   = (const float*)d_in[5];
    const float* wq     = (const float*)d_in[6];
    const float* wk     = (const float*)d_in[7];
    const float* wv     = (const float*)d_in[8];
    const float* wo     = (const float*)d_in[9];
    const float* bq     = (const float*)d_in[10];
    const float* bk     = (const float*)d_in[11];
    const float* bv     = (const float*)d_in[12];
    const float* bo     = (const float*)d_in[13];
    const float* ffn_w1 = (const float*)d_in[14];
    const float* ffn_b1 = (const float*)d_in[15];
    const float* ffn_w2 = (const float*)d_in[16];
    const float* ffn_b2 = (const float*)d_in[17];
    const float* pw_w   = (const float*)d_in[18];
    const float* pw_b   = (const float*)d_in[19];
    float* out = (float*)d_out;

    float *px, *ph, *pq, *pk, *pv, *pf;
    float2* pst;
    cudaGetSymbolAddress((void**)&px, g_x);
    cudaGetSymbolAddress((void**)&ph, g_h);
    cudaGetSymbolAddress((void**)&pq, g_q);
    cudaGetSymbolAddress((void**)&pk, g_k);
    cudaGetSymbolAddress((void**)&pv, g_v);
    cudaGetSymbolAddress((void**)&pf, g_f1);
    cudaGetSymbolAddress((void**)&pst, g_stats);

    size_t smemRow = (size_t)(2 * LL * DH + DH * DH + 3 * DH + LL) * sizeof(float); // 109120
    size_t smemCol = (size_t)(2 * SS * DH + DH * DH + 3 * DH + SS) * sizeof(float); // 34624
    cudaFuncSetAttribute(attn_kernel, cudaFuncAttributeMaxDynamicSharedMemorySize, 112640);

    dim3 lnBlk(32, 8);
    dim3 gQKV(TT / BM, 6);
    dim3 g192(TT / BM, CC / BN);    // (256, 2)
    dim3 g768(TT / BM, C4 / BN);    // (256, 8)

    embed_kernel<<<TT, CC>>>(tokens, emb, proj_w, proj_b, px);

    for (int i = 0; i < NBLK; i++) {
        for (int dir = 0; dir < 2; dir++) {
            const float* lg = ln_g + (size_t)(i * 3 + dir) * CC;
            const float* lb = ln_b + (size_t)(i * 3 + dir) * CC;
            ln_stats_kernel<<<TT / 8, lnBlk>>>(px, pst);

            size_t woff = ((size_t)i * 2 + dir) * CC * CC;
            size_t boff = ((size_t)i * 2 + dir) * CC;
            qkv_kernel<<<gQKV, 256>>>(px, wq + woff, wk + woff, wv + woff,
                                      bq + boff, bk + boff, bv + boff,
                                      pq, pk, pv, pst, lg, lb);

            if (dir == 0) {
                attn_kernel<<<dim3(BB * SS, HH), 256, smemRow>>>(pq, pk, pv, ph, LL, 0);
            } else {
                attn_kernel<<<dim3(BB * LL, HH), 256, smemCol>>>(pq, pk, pv, ph, SS, 1);
            }

            gemm_kernel<<<g192, 256>>>(ph, wo + woff, bo + boff, px, CC, CC, 0, 1);
        }
        const float* lg = ln_g + (size_t)(i * 3 + 2) * CC;
        const float* lb = ln_b + (size_t)(i * 3 + 2) * CC;
        ln_stats_kernel<<<TT / 8, lnBlk>>>(px, pst);
        gemm_ln_kernel<<<g768, 256>>>(px, ffn_w1 + (size_t)i * C4 * CC, ffn_b1 + (size_t)i * C4,
                                      pf, CC, C4, 3, 0, pst, lg, lb);
        gemm_kernel<<<g192, 256>>>(pf, ffn_w2 + (size_t)i * CC * C4, ffn_b2 + (size_t)i * CC,
                                   px, C4, CC, 0, 1);
    }

    final_kernel<<<TT / 8, lnBlk>>>(px, pw_w, pw_b, out);
}

// round 14
// speedup vs baseline: 1.9714x; 1.2516x over previous
#include <cuda_runtime.h>
#include <cuda_bf16.h>
#include <math.h>

// ---------------- problem constants ----------------
#define BB 2
#define SS 64
#define LL 256
#define CC 192
#define C4 768
#define HH 4
#define DH 48
#define TT (BB*SS*LL)      // 32768 tokens
#define NBLK 6

// ---------------- scratch ----------------
__device__ float g_x[TT*CC];
__device__ float g_h[TT*CC];
__device__ float g_q[TT*CC];
__device__ float g_k[TT*CC];
__device__ float g_v[TT*CC];
__device__ float g_f1[TT*C4];
__device__ float2 g_stats[TT];   // per-token (mean, rstd)

__device__ __forceinline__ float elu1(float v) { return v > 0.0f ? v + 1.0f : expf(v); }
__device__ __forceinline__ float gelu_exact(float v) {
    return 0.5f * v * (1.0f + erff(v * 0.70710678118654752f));
}
__device__ __forceinline__ unsigned int packbf(float a, float b) {
    __nv_bfloat162 h = __floats2bfloat162_rn(a, b);
    return *(unsigned int*)&h;
}

// ============================================================
// Kernel 1: embed + proj + rotary
// ============================================================
__global__ void embed_kernel(const int* __restrict__ tokens,
                             const float* __restrict__ emb,
                             const float* __restrict__ pw,
                             const float* __restrict__ pb,
                             float* __restrict__ out) {
    int t = blockIdx.x;
    int c = threadIdx.x;
    __shared__ float e[64];
    __shared__ float xv[CC];
    __shared__ float invf[96];
    if (c < 64) e[c] = emb[tokens[t] * 64 + c];
    if (c >= 64 && c < 160) {
        int j = c - 64;
        invf[j] = powf(10000.0f, -(float)j / 96.0f);
    }
    __syncthreads();
    float s = pb[c];
    const float* wr = pw + c * 64;
    #pragma unroll
    for (int i = 0; i < 64; i++) s += e[i] * wr[i];
    xv[c] = s;
    __syncthreads();
    int l = t & (LL - 1);
    int c2 = (c < 96) ? c : c - 96;
    float a = (float)l * invf[c2];
    float cs = cosf(a), sn = sinf(a);
    float rot = (c < 96) ? -xv[c + 96] : xv[c - 96];
    out[(size_t)t * CC + c] = s * cs + rot * sn;
}

// ============================================================
// Kernel 2: LN stats only — (mean, rstd) per token
// ============================================================
__global__ void ln_stats_kernel(const float* __restrict__ x,
                                float2* __restrict__ stats) {
    int t = blockIdx.x * 8 + threadIdx.y;
    int lane = threadIdx.x;
    const float* xr = x + (size_t)t * CC;
    float s = 0.f, ss = 0.f;
    #pragma unroll
    for (int i = 0; i < 6; i++) {
        float v = xr[lane + i * 32];
        s += v; ss += v * v;
    }
    #pragma unroll
    for (int o = 16; o; o >>= 1) {
        s  += __shfl_xor_sync(0xffffffffu, s, o);
        ss += __shfl_xor_sync(0xffffffffu, ss, o);
    }
    if (lane == 0) {
        float m   = s * (1.0f / CC);
        float var = ss * (1.0f / CC) - m * m;
        stats[t] = make_float2(m, rsqrtf(var + 1e-5f));
    }
}

// ============================================================
// bf16 tensor-core GEMM (mma.m16n8k16, fp32 accum), fragment-major smem,
// ping-pong pipeline, optional fused LN on the A path.
// Block tile 128x96, 8 warps (4x2), warp tile 32x48 (2x6 mma).
// smem (u32): A tile = 8 mtiles * 32 lanes * 4 slots = 1024
//             B tile = 12 ntiles * 32 lanes * 2 slots = 768
// ============================================================
#define BM 128
#define BN 96
#define BK 16
#define ASZU 1024
#define BSZU 768

__device__ __forceinline__ void gemm_stage_bf16(
        unsigned int* As, unsigned int* Bs,
        const float4 aPre[2], const float4 bPre[2], int tid) {
    #pragma unroll
    for (int i = 0; i < 2; i++) {
        int lin = tid + i * 256;
        int m  = lin >> 2;
        int kq = (lin & 3) << 2;             // 0,4,8,12
        int mtile = m >> 4, r = m & 15;
        int gid = r & 7, rh = r >> 3;
        unsigned int p0 = packbf(aPre[i].x, aPre[i].y);
        unsigned int p1 = packbf(aPre[i].z, aPre[i].w);
        int pa = kq >> 1;                    // 0,2,4,6
        int pb = pa + 1;
        As[mtile * 128 + (gid * 4 + (pa & 3)) * 4 + (rh + ((pa >> 2) << 1))] = p0;
        As[mtile * 128 + (gid * 4 + (pb & 3)) * 4 + (rh + ((pb >> 2) << 1))] = p1;
    }
    #pragma unroll
    for (int i = 0; i < 2; i++) {
        int lin = tid + i * 256;
        if (lin < BN * 4) {
            int n  = lin >> 2;
            int kq = (lin & 3) << 2;
            int ntile = n >> 3, c = n & 7;
            unsigned int p0 = packbf(bPre[i].x, bPre[i].y);
            unsigned int p1 = packbf(bPre[i].z, bPre[i].w);
            int pa = kq >> 1, pb = pa + 1;
            Bs[ntile * 64 + (c * 4 + (pa & 3)) * 2 + (pa >> 2)] = p0;
            Bs[ntile * 64 + (c * 4 + (pb & 3)) * 2 + (pb >> 2)] = p1;
        }
    }
}

template<bool LN>
__device__ __forceinline__ void gemm_body(
        const float* __restrict__ A, const float* __restrict__ W,
        const float* __restrict__ bias, float* __restrict__ Cout,
        int K, int N, int act, int accFlag, int rowBlk, int colBlk,
        unsigned int* AsBuf, unsigned int* BsBuf,
        const float2* __restrict__ stats,
        const float* __restrict__ lnG, const float* __restrict__ lnB) {
    int tid  = threadIdx.x;
    int lane = tid & 31;
    int warp = tid >> 5;
    int warpM = warp >> 1;
    int warpN = warp & 1;
    int gid = lane >> 2;
    int tig = lane & 3;
    int row0 = rowBlk * BM;
    int col0 = colBlk * BN;

    float acc[2][6][4];
    #pragma unroll
    for (int i = 0; i < 2; i++)
        #pragma unroll
        for (int j = 0; j < 6; j++)
            #pragma unroll
            for (int q = 0; q < 4; q++) acc[i][j][q] = 0.f;

    int aM0 = (tid) >> 2,       aK = (tid & 3) << 2;
    int aM1 = (tid + 256) >> 2;
    int bN0 = tid >> 2,         bK = (tid & 3) << 2;
    int bN1 = (tid + 256) >> 2;
    const float* aPtr0 = A + (size_t)(row0 + aM0) * K + aK;
    const float* aPtr1 = A + (size_t)(row0 + aM1) * K + aK;
    const float* bPtr0 = W + (size_t)(col0 + bN0) * K + bK;
    const float* bPtr1 = W + (size_t)(col0 + (bN1 < BN ? bN1 : 0)) * K + bK;
    bool bHas1 = (tid < (BN * 4 - 256));

    float2 st0, st1;
    if (LN) {
        st0 = stats[row0 + aM0];
        st1 = stats[row0 + aM1];
    }

    float4 aPre[2]; float4 bPre[2];
    aPre[0] = *(const float4*)aPtr0;
    aPre[1] = *(const float4*)aPtr1;
    bPre[0] = *(const float4*)bPtr0;
    bPre[1] = bHas1 ? *(const float4*)bPtr1 : make_float4(0.f,0.f,0.f,0.f);
    if (LN) {
        float4 g4 = *(const float4*)(lnG + aK);
        float4 b4 = *(const float4*)(lnB + aK);
        aPre[0].x = (aPre[0].x - st0.x) * st0.y * g4.x + b4.x;
        aPre[0].y = (aPre[0].y - st0.x) * st0.y * g4.y + b4.y;
        aPre[0].z = (aPre[0].z - st0.x) * st0.y * g4.z + b4.z;
        aPre[0].w = (aPre[0].w - st0.x) * st0.y * g4.w + b4.w;
        aPre[1].x = (aPre[1].x - st1.x) * st1.y * g4.x + b4.x;
        aPre[1].y = (aPre[1].y - st1.x) * st1.y * g4.y + b4.y;
        aPre[1].z = (aPre[1].z - st1.x) * st1.y * g4.z + b4.z;
        aPre[1].w = (aPre[1].w - st1.x) * st1.y * g4.w + b4.w;
    }

    int NT = K / BK;
    gemm_stage_bf16(AsBuf, BsBuf, aPre, bPre, tid);
    __syncthreads();

    for (int it = 0; it < NT; it++) {
        int cur = it & 1;
        if (it + 1 < NT) {
            int off = (it + 1) * BK;
            aPre[0] = *(const float4*)(aPtr0 + off);
            aPre[1] = *(const float4*)(aPtr1 + off);
            bPre[0] = *(const float4*)(bPtr0 + off);
            if (bHas1) bPre[1] = *(const float4*)(bPtr1 + off);
            if (LN) {
                int kb = off + aK;
                float4 g4 = *(const float4*)(lnG + kb);
                float4 b4 = *(const float4*)(lnB + kb);
                aPre[0].x = (aPre[0].x - st0.x) * st0.y * g4.x + b4.x;
                aPre[0].y = (aPre[0].y - st0.x) * st0.y * g4.y + b4.y;
                aPre[0].z = (aPre[0].z - st0.x) * st0.y * g4.z + b4.z;
                aPre[0].w = (aPre[0].w - st0.x) * st0.y * g4.w + b4.w;
                aPre[1].x = (aPre[1].x - st1.x) * st1.y * g4.x + b4.x;
                aPre[1].y = (aPre[1].y - st1.x) * st1.y * g4.y + b4.y;
                aPre[1].z = (aPre[1].z - st1.x) * st1.y * g4.z + b4.z;
                aPre[1].w = (aPre[1].w - st1.x) * st1.y * g4.w + b4.w;
            }
        }
        unsigned int* Ac = AsBuf + cur * ASZU;
        unsigned int* Bc = BsBuf + cur * BSZU;
        {
            uint4 af[2]; uint2 bf[6];
            #pragma unroll
            for (int mt = 0; mt < 2; mt++) {
                int mtile = warpM * 2 + mt;
                af[mt] = ((const uint4*)Ac)[mtile * 32 + lane];
            }
            #pragma unroll
            for (int nt = 0; nt < 6; nt++) {
                int ntile = warpN * 6 + nt;
                bf[nt] = ((const uint2*)Bc)[ntile * 32 + lane];
            }
            #pragma unroll
            for (int mt = 0; mt < 2; mt++)
                #pragma unroll
                for (int nt = 0; nt < 6; nt++) {
                    asm volatile(
                        "mma.sync.aligned.m16n8k16.row.col.f32.bf16.bf16.f32 "
                        "{%0,%1,%2,%3}, {%4,%5,%6,%7}, {%8,%9}, {%0,%1,%2,%3};"
                        : "+f"(acc[mt][nt][0]), "+f"(acc[mt][nt][1]),
                          "+f"(acc[mt][nt][2]), "+f"(acc[mt][nt][3])
                        : "r"(af[mt].x), "r"(af[mt].y), "r"(af[mt].z), "r"(af[mt].w),
                          "r"(bf[nt].x), "r"(bf[nt].y));
                }
        }
        if (it + 1 < NT) {
            gemm_stage_bf16(AsBuf + (cur ^ 1) * ASZU, BsBuf + (cur ^ 1) * BSZU,
                            aPre, bPre, tid);
            __syncthreads();
        }
    }

    #pragma unroll
    for (int mt = 0; mt < 2; mt++) {
        int r0 = row0 + warpM * 32 + mt * 16 + gid;
        #pragma unroll
        for (int nt = 0; nt < 6; nt++) {
            int c0 = col0 + warpN * 48 + nt * 8 + tig * 2;
            #pragma unroll
            for (int half = 0; half < 2; half++) {
                int r = r0 + half * 8;
                #pragma unroll
                for (int q = 0; q < 2; q++) {
                    int c = c0 + q;
                    float v = acc[mt][nt][half * 2 + q] + bias[c];
                    if (act == 1)      v = elu1(v) * 0.14433756729740643f;
                    else if (act == 2) v = elu1(v);
                    else if (act == 3) v = gelu_exact(v);
                    size_t idx = (size_t)r * N + c;
                    if (accFlag) v += Cout[idx];
                    Cout[idx] = v;
                }
            }
        }
    }
}

__global__ __launch_bounds__(256) void gemm_kernel(
        const float* __restrict__ A, const float* __restrict__ W,
        const float* __restrict__ bias, float* __restrict__ Cout,
        int K, int N, int act, int accFlag) {
    __shared__ unsigned int As[2 * ASZU];
    __shared__ unsigned int Bs[2 * BSZU];
    gemm_body<false>(A, W, bias, Cout, K, N, act, accFlag, blockIdx.x, blockIdx.y,
                     As, Bs, nullptr, nullptr, nullptr);
}

__global__ __launch_bounds__(256) void gemm_ln_kernel(
        const float* __restrict__ A, const float* __restrict__ W,
        const float* __restrict__ bias, float* __restrict__ Cout,
        int K, int N, int act, int accFlag,
        const float2* __restrict__ stats,
        const float* __restrict__ lnG, const float* __restrict__ lnB) {
    __shared__ unsigned int As[2 * ASZU];
    __shared__ unsigned int Bs[2 * BSZU];
    gemm_body<true>(A, W, bias, Cout, K, N, act, accFlag, blockIdx.x, blockIdx.y,
                    As, Bs, stats, lnG, lnB);
}

__global__ __launch_bounds__(256) void qkv_kernel(
        const float* __restrict__ A,
        const float* __restrict__ wq, const float* __restrict__ wk, const float* __restrict__ wv,
        const float* __restrict__ bq, const float* __restrict__ bk, const float* __restrict__ bv,
        float* __restrict__ oq, float* __restrict__ ok, float* __restrict__ ov,
        const float2* __restrict__ stats,
        const float* __restrict__ lnG, const float* __restrict__ lnB) {
    __shared__ unsigned int As[2 * ASZU];
    __shared__ unsigned int Bs[2 * BSZU];
    int sel = blockIdx.y >> 1;
    int cb  = blockIdx.y & 1;
    const float* W  = sel == 0 ? wq : (sel == 1 ? wk : wv);
    const float* bi = sel == 0 ? bq : (sel == 1 ? bk : bv);
    float* Cout     = sel == 0 ? oq : (sel == 1 ? ok : ov);
    int act         = sel == 0 ? 1  : (sel == 1 ? 2  : 0);
    gemm_body<true>(A, W, bi, Cout, CC, CC, act, 0, blockIdx.x, cb,
                    As, Bs, stats, lnG, lnB);
}

// ============================================================
// Kernel 4: linear attention (unchanged from R11/R12 win)
// ============================================================
__global__ __launch_bounds__(256) void attn_kernel(
        const float* __restrict__ q, const float* __restrict__ k,
        const float* __restrict__ v, float* __restrict__ o,
        int N, int isCol) {
    extern __shared__ float sm[];
    float* ks   = sm;
    float* vs   = ks + N * DH;
    float* kv   = vs + N * DH;
    float* psum = kv + DH * DH;
    float* ksum = psum + 2 * DH;
    float* zz   = ksum + DH;
    int g = blockIdx.x, h = blockIdx.y;
    int tid = threadIdx.x;

    for (int lin = tid; lin < N * 12; lin += 256) {
        int n = lin / 12;
        int j = lin - n * 12;
        int t = isCol ? ((((g >> 8) * SS + n) << 8) + (g & 255)) : g * N + n;
        size_t base = (size_t)t * CC + h * DH + j * 4;
        ((float4*)ks)[lin] = *(const float4*)(k + base);
        ((float4*)vs)[lin] = *(const float4*)(v + base);
    }
    __syncthreads();

    if (tid < 72) {
        int dp = tid % 12;
        int eo = tid / 12;
        float acc[4][8];
        #pragma unroll
        for (int i = 0; i < 4; i++)
            #pragma unroll
            for (int j = 0; j < 8; j++) acc[i][j] = 0.f;
        for (int n = 0; n < N; n++) {
            float4 kk = ((const float4*)ks)[n * 12 + dp];
            float4 va = ((const float4*)vs)[n * 12 + eo * 2];
            float4 vb = ((const float4*)vs)[n * 12 + eo * 2 + 1];
            float kr[4] = {kk.x, kk.y, kk.z, kk.w};
            float vv[8] = {va.x, va.y, va.z, va.w, vb.x, vb.y, vb.z, vb.w};
            #pragma unroll
            for (int i = 0; i < 4; i++)
                #pragma unroll
                for (int j = 0; j < 8; j++) acc[i][j] += kr[i] * vv[j];
        }
        #pragma unroll
        for (int i = 0; i < 4; i++) {
            ((float4*)kv)[(dp * 4 + i) * 12 + eo * 2]     =
                make_float4(acc[i][0], acc[i][1], acc[i][2], acc[i][3]);
            ((float4*)kv)[(dp * 4 + i) * 12 + eo * 2 + 1] =
                make_float4(acc[i][4], acc[i][5], acc[i][6], acc[i][7]);
        }
    } else if (tid >= 96 && tid < 192) {
        int idx = tid - 96;
        int d  = idx % DH;
        int ch = idx / DH;
        int half = N >> 1;
        int n0 = ch * half;
        float s = 0.f;
        for (int n = n0; n < n0 + half; n++) s += ks[n * DH + d];
        psum[ch * DH + d] = s;
    }
    __syncthreads();

    if (tid < DH) ksum[tid] = psum[tid] + psum[DH + tid];
    __syncthreads();

    if (tid < N) {
        int n = tid;
        int t = isCol ? ((((g >> 8) * SS + n) << 8) + (g & 255)) : g * N + n;
        const float* qp = q + (size_t)t * CC + h * DH;
        float s = 0.f;
        #pragma unroll
        for (int j = 0; j < 12; j++) {
            float4 f = *(const float4*)(qp + j * 4);
            s += f.x * ksum[j*4] + f.y * ksum[j*4+1] + f.z * ksum[j*4+2] + f.w * ksum[j*4+3];
        }
        zz[n] = 1.0f / (s + 1e-6f);
    }
    __syncthreads();

    int items = (N >> 2) * 6;
    for (int item = tid; item < items; item += 256) {
        int np = item / 6, eo = item % 6;
        int n0 = np * 4;
        const float* qp[4];
        int tt[4];
        #pragma unroll
        for (int i = 0; i < 4; i++) {
            int n = n0 + i;
            tt[i] = isCol ? ((((g >> 8) * SS + n) << 8) + (g & 255)) : g * N + n;
            qp[i] = q + (size_t)tt[i] * CC + h * DH;
        }
        float acc[4][8];
        #pragma unroll
        for (int i = 0; i < 4; i++)
            #pragma unroll
            for (int j = 0; j < 8; j++) acc[i][j] = 0.f;

        for (int j = 0; j < 12; j++) {
            float qr[4][4];
            #pragma unroll
            for (int i = 0; i < 4; i++) {
                float4 f = *(const float4*)(qp[i] + j * 4);
                qr[i][0] = f.x; qr[i][1] = f.y; qr[i][2] = f.z; qr[i][3] = f.w;
            }
            #pragma unroll
            for (int dd = 0; dd < 4; dd++) {
                int d = j * 4 + dd;
                float4 a = ((const float4*)kv)[d * 12 + eo * 2];
                float4 b = ((const float4*)kv)[d * 12 + eo * 2 + 1];
                #pragma unroll
                for (int i = 0; i < 4; i++) {
                    float qd = qr[i][dd];
                    acc[i][0] += qd * a.x; acc[i][1] += qd * a.y;
                    acc[i][2] += qd * a.z; acc[i][3] += qd * a.w;
                    acc[i][4] += qd * b.x; acc[i][5] += qd * b.y;
                    acc[i][6] += qd * b.z; acc[i][7] += qd * b.w;
                }
            }
        }
        #pragma unroll
        for (int i = 0; i < 4; i++) {
            float z = zz[n0 + i];
            float* op = o + (size_t)tt[i] * CC + h * DH + eo * 8;
            *(float4*)op       = make_float4(acc[i][0]*z, acc[i][1]*z, acc[i][2]*z, acc[i][3]*z);
            *(float4*)(op + 4) = make_float4(acc[i][4]*z, acc[i][5]*z, acc[i][6]*z, acc[i][7]*z);
        }
    }
}

// ============================================================
// Kernel 5: head
// ============================================================
__global__ void final_kernel(const float* __restrict__ x,
                             const float* __restrict__ pw,
                             const float* __restrict__ pb,
                             float* __restrict__ out) {
    int t = blockIdx.x * 8 + threadIdx.y;
    int lane = threadIdx.x;
    const float* xr = x + (size_t)t * CC;
    float s = 0.f;
    #pragma unroll
    for (int i = 0; i < 6; i++) {
        int c = lane + i * 32;
        s += xr[c] * pw[c];
    }
    #pragma unroll
    for (int o = 16; o; o >>= 1) s += __shfl_xor_sync(0xffffffffu, s, o);
    if (lane == 0) {
        float ov = s + pb[0];
        float sp = (ov > 20.f) ? ov : log1pf(expf(ov));
        out[t] = 1.0f / (1.0f + expf(-sp));
    }
}

// ============================================================
// Host orchestration
// ============================================================
extern "C" void kernel_launch(void* const* d_in, const int* in_sizes, int n_in,
                              void* d_out, int out_size) {
    const int*   tokens = (const int*)  d_in[0];
    const float* emb    = (const float*)d_in[1];
    const float* proj_w = (const float*)d_in[2];
    const float* proj_b = (const float*)d_in[3];
    const float* ln_g   = (const float*)d_in[4];
    const float* ln_b   = (const float*)d_in[5];
    const float* wq     = (const float*)d_in[6];
    const float* wk     = (const float*)d_in[7];
    const float* wv     = (const float*)d_in[8];
    const float* wo     = (const float*)d_in[9];
    const float* bq     = (const float*)d_in[10];
    const float* bk     = (const float*)d_in[11];
    const float* bv     = (const float*)d_in[12];
    const float* bo     = (const float*)d_in[13];
    const float* ffn_w1 = (const float*)d_in[14];
    const float* ffn_b1 = (const float*)d_in[15];
    const float* ffn_w2 = (const float*)d_in[16];
    const float* ffn_b2 = (const float*)d_in[17];
    const float* pw_w   = (const float*)d_in[18];
    const float* pw_b   = (const float*)d_in[19];
    float* out = (float*)d_out;

    float *px, *ph, *pq, *pk, *pv, *pf;
    float2* pst;
    cudaGetSymbolAddress((void**)&px, g_x);
    cudaGetSymbolAddress((void**)&ph, g_h);
    cudaGetSymbolAddress((void**)&pq, g_q);
    cudaGetSymbolAddress((void**)&pk, g_k);
    cudaGetSymbolAddress((void**)&pv, g_v);
    cudaGetSymbolAddress((void**)&pf, g_f1);
    cudaGetSymbolAddress((void**)&pst, g_stats);

    size_t smemRow = (size_t)(2 * LL * DH + DH * DH + 3 * DH + LL) * sizeof(float); // 109120
    size_t smemCol = (size_t)(2 * SS * DH + DH * DH + 3 * DH + SS) * sizeof(float); // 34624
    cudaFuncSetAttribute(attn_kernel, cudaFuncAttributeMaxDynamicSharedMemorySize, 112640);

    dim3 lnBlk(32, 8);
    dim3 gQKV(TT / BM, 6);
    dim3 g192(TT / BM, CC / BN);    // (256, 2)
    dim3 g768(TT / BM, C4 / BN);    // (256, 8)

    embed_kernel<<<TT, CC>>>(tokens, emb, proj_w, proj_b, px);

    for (int i = 0; i < NBLK; i++) {
        for (int dir = 0; dir < 2; dir++) {
            const float* lg = ln_g + (size_t)(i * 3 + dir) * CC;
            const float* lb = ln_b + (size_t)(i * 3 + dir) * CC;
            ln_stats_kernel<<<TT / 8, lnBlk>>>(px, pst);

            size_t woff = ((size_t)i * 2 + dir) * CC * CC;
            size_t boff = ((size_t)i * 2 + dir) * CC;
            qkv_kernel<<<gQKV, 256>>>(px, wq + woff, wk + woff, wv + woff,
                                      bq + boff, bk + boff, bv + boff,
                                      pq, pk, pv, pst, lg, lb);

            if (dir == 0) {
                attn_kernel<<<dim3(BB * SS, HH), 256, smemRow>>>(pq, pk, pv, ph, LL, 0);
            } else {
                attn_kernel<<<dim3(BB * LL, HH), 256, smemCol>>>(pq, pk, pv, ph, SS, 1);
            }

            gemm_kernel<<<g192, 256>>>(ph, wo + woff, bo + boff, px, CC, CC, 0, 1);
        }
        const float* lg = ln_g + (size_t)(i * 3 + 2) * CC;
        const float* lb = ln_b + (size_t)(i * 3 + 2) * CC;
        ln_stats_kernel<<<TT / 8, lnBlk>>>(px, pst);
        gemm_ln_kernel<<<g768, 256>>>(px, ffn_w1 + (size_t)i * C4 * CC, ffn_b1 + (size_t)i * C4,
                                      pf, CC, C4, 3, 0, pst, lg, lb);
        gemm_kernel<<<g192, 256>>>(pf, ffn_w2 + (size_t)i * CC * C4, ffn_b2 + (size_t)i * CC,
                                   px, C4, CC, 0, 1);
    }

    final_kernel<<<TT / 8, lnBlk>>>(px, pw_w, pw_b, out);
}